// round 5
// baseline (speedup 1.0000x reference)
#include <cuda_runtime.h>
#include <cuda_bf16.h>
#include <cstdint>

#define BB   8
#define TT   2048
#define NXC  1024
#define NHC  1024
#define MTOT (BB * TT)   // 16384

// ---------------------------------------------------------------------------
// Scratch (device globals — no allocation allowed anywhere)
// ---------------------------------------------------------------------------
__device__ __nv_bfloat16 g_xhi[(size_t)MTOT * NXC], g_xlo[(size_t)MTOT * NXC];
__device__ __nv_bfloat16 g_wqhi[NHC * NXC], g_wqlo[NHC * NXC];
__device__ __nv_bfloat16 g_wkhi[NHC * NXC], g_wklo[NHC * NXC];
__device__ __nv_bfloat16 g_wvhi[NHC * NXC], g_wvlo[NHC * NXC];
__device__ __nv_bfloat16 g_wohi[NHC * NHC], g_wolo[NHC * NHC];
__device__ __nv_bfloat16 g_qhi[(size_t)MTOT * NHC], g_qlo[(size_t)MTOT * NHC];
__device__ __nv_bfloat16 g_khi[(size_t)MTOT * NHC], g_klo[(size_t)MTOT * NHC];
__device__ __nv_bfloat16 g_vthi[(size_t)NHC * MTOT], g_vtlo[(size_t)NHC * MTOT];
__device__ float         g_s[(size_t)BB * TT * TT];
__device__ __nv_bfloat16 g_phi[(size_t)BB * TT * TT], g_plo[(size_t)BB * TT * TT];
__device__ __nv_bfloat16 g_ohi[(size_t)MTOT * NHC], g_olo[(size_t)MTOT * NHC];

// ---------------------------------------------------------------------------
// PTX helpers (sm_80-era only — must be valid under compute_103 virtual arch)
// ---------------------------------------------------------------------------
__device__ __forceinline__ uint32_t smem_u32(const void* p) {
    uint32_t a;
    asm("{ .reg .u64 t; cvta.to.shared.u64 t, %1; cvt.u32.u64 %0, t; }"
        : "=r"(a) : "l"(p));
    return a;
}
__device__ __forceinline__ void cpa16(uint32_t dst, const void* src) {
    asm volatile("cp.async.cg.shared.global [%0], [%1], 16;\n" :: "r"(dst), "l"(src));
}
__device__ __forceinline__ void cpa_commit() {
    asm volatile("cp.async.commit_group;\n" ::: "memory");
}
template <int N>
__device__ __forceinline__ void cpa_wait() {
    asm volatile("cp.async.wait_group %0;\n" :: "n"(N) : "memory");
}
__device__ __forceinline__ void ldsm4(uint32_t* r, uint32_t addr) {
    asm volatile("ldmatrix.sync.aligned.m8n8.x4.shared.b16 {%0,%1,%2,%3}, [%4];"
                 : "=r"(r[0]), "=r"(r[1]), "=r"(r[2]), "=r"(r[3]) : "r"(addr));
}
__device__ __forceinline__ void mma16816(float* d, const uint32_t* a, const uint32_t* b) {
    asm volatile(
        "mma.sync.aligned.m16n8k16.row.col.f32.bf16.bf16.f32 "
        "{%0,%1,%2,%3}, {%4,%5,%6,%7}, {%8,%9}, {%0,%1,%2,%3};"
        : "+f"(d[0]), "+f"(d[1]), "+f"(d[2]), "+f"(d[3])
        : "r"(a[0]), "r"(a[1]), "r"(a[2]), "r"(a[3]), "r"(b[0]), "r"(b[1]));
}
__device__ __forceinline__ uint32_t swz(uint32_t off) {
    return off ^ ((off >> 3) & 0x70);
}

// ---------------------------------------------------------------------------
// mma.sync NT GEMM:  C[M,N] = alpha * (A[M,K] @ B[N,K]^T)
// A = Ahi + Alo, B = Bhi + Blo (bf16 split); fp32 accumulate; 3-term product.
// Tile: 256(M) x 128(N), 512 threads, 16 warps as 4x4, warp tile 64x32.
// K chunks of 64 bf16; 2-stage cp.async double buffer (96 KB/stage).
// grid = (N/128, M/256, batch). OUTBF=1: write bf16 hi/lo; else fp32.
// ---------------------------------------------------------------------------
#define A_HI 0
#define A_LO 32768
#define B_HI 65536
#define B_LO 81920
#define STG  98304                    // 96 KB per stage
#define SMEM_TOTAL (2 * STG)          // 192 KB

template <int OUTBF>
__global__ void __launch_bounds__(512, 1) gemm_mma(
    const __nv_bfloat16* __restrict__ Ahi, const __nv_bfloat16* __restrict__ Alo,
    const __nv_bfloat16* __restrict__ Bhi, const __nv_bfloat16* __restrict__ Blo,
    float* __restrict__ C, __nv_bfloat16* __restrict__ Chi, __nv_bfloat16* __restrict__ Clo,
    int K, int lda, int ldb, int ldc,
    long long sA, long long sB, long long sC, float alpha)
{
    extern __shared__ __align__(1024) char smem[];
    const uint32_t sbase = smem_u32(smem);
    const int tid = threadIdx.x;
    const int wid = tid >> 5, lane = tid & 31;
    const long long bz = blockIdx.z;
    const int row0 = blockIdx.y * 256;
    const int col0 = blockIdx.x * 128;

    const char* gAhi = (const char*)(Ahi + bz * sA + (long long)row0 * lda);
    const char* gAlo = (const char*)(Alo + bz * sA + (long long)row0 * lda);
    const char* gBhi = (const char*)(Bhi + bz * sB + (long long)col0 * ldb);
    const char* gBlo = (const char*)(Blo + bz * sB + (long long)col0 * ldb);
    const long long ldab = (long long)lda * 2;
    const long long ldbb = (long long)ldb * 2;

    // Stage-load addressing: 512 threads, 8 x 16B chunks per 128B row
    const uint32_t l_r  = (uint32_t)tid >> 3;           // 0..63 base row
    const uint32_t l_cb = ((uint32_t)tid & 7) << 4;     // 16B chunk in row

    auto load_stage = [&](int c) {
        const uint32_t sb = sbase + ((c & 1) ? (uint32_t)STG : 0u);
        const long long kb = (long long)c * 128;        // 64 bf16 = 128 B
#pragma unroll
        for (int i = 0; i < 4; i++) {                   // A: 256 rows
            const uint32_t r = l_r + (uint32_t)(i << 6);
            const uint32_t off = swz((r << 7) + l_cb);
            const long long ga = (long long)r * ldab + kb + l_cb;
            cpa16(sb + A_HI + off, gAhi + ga);
            cpa16(sb + A_LO + off, gAlo + ga);
        }
#pragma unroll
        for (int i = 0; i < 2; i++) {                   // B: 128 rows
            const uint32_t r = l_r + (uint32_t)(i << 6);
            const uint32_t off = swz((r << 7) + l_cb);
            const long long gb = (long long)r * ldbb + kb + l_cb;
            cpa16(sb + B_HI + off, gBhi + gb);
            cpa16(sb + B_LO + off, gBlo + gb);
        }
        cpa_commit();
    };

    const int NC = K >> 6;
    const int warp_m = wid & 3;       // 4 warps down M (64 rows each)
    const int warp_n = wid >> 2;      // 4 warps across N (32 cols each)
    const int lrow = lane & 15;
    const uint32_t klane = (lane >> 4) << 4;

    float acc[4][4][4];               // mt x nt x frag
#pragma unroll
    for (int i = 0; i < 4; i++)
#pragma unroll
        for (int j = 0; j < 4; j++)
#pragma unroll
            for (int k = 0; k < 4; k++) acc[i][j][k] = 0.0f;

    load_stage(0);

    for (int c = 0; c < NC; c++) {
        if (c + 1 < NC) { load_stage(c + 1); cpa_wait<1>(); }
        else            { cpa_wait<0>(); }
        __syncthreads();

        const uint32_t sb = sbase + ((c & 1) ? (uint32_t)STG : 0u);
#pragma unroll
        for (int ks = 0; ks < 4; ks++) {
            const uint32_t kbyte = (ks << 5) + klane;
            // B fragments for this warp's 32 columns (kept live: 16 regs)
            uint32_t bh[2][4], bl[2][4];
#pragma unroll
            for (int ng = 0; ng < 2; ng++) {
                const uint32_t off =
                    swz((uint32_t)((warp_n * 32 + ng * 16 + lrow) << 7) + kbyte);
                ldsm4(bh[ng], sb + B_HI + off);
                ldsm4(bl[ng], sb + B_LO + off);
            }
            // A fragments loaded per-mt to bound register pressure
#pragma unroll
            for (int mt = 0; mt < 4; mt++) {
                const uint32_t off =
                    swz((uint32_t)((warp_m * 64 + mt * 16 + lrow) << 7) + kbyte);
                uint32_t ah[4], al[4];
                ldsm4(ah, sb + A_HI + off);
                ldsm4(al, sb + A_LO + off);
#pragma unroll
                for (int nt = 0; nt < 4; nt++) {
                    const int ng = nt >> 1, j = nt & 1;
                    uint32_t B0[2] = { bh[ng][j], bh[ng][j + 2] };
                    uint32_t L0[2] = { bl[ng][j], bl[ng][j + 2] };
                    mma16816(acc[mt][nt], ah, B0);   // hi*hi
                    mma16816(acc[mt][nt], al, B0);   // lo*hi
                    mma16816(acc[mt][nt], ah, L0);   // hi*lo
                }
            }
        }
        __syncthreads();
    }

    // Epilogue: c-frag rows lane/4 (+8), cols 2*(lane%4)+1
    const int rw = row0 + warp_m * 64 + (lane >> 2);
    const int cw = col0 + warp_n * 32 + (lane & 3) * 2;
#pragma unroll
    for (int mt = 0; mt < 4; mt++)
#pragma unroll
        for (int nt = 0; nt < 4; nt++) {
            const int cc = cw + nt * 8;
#pragma unroll
            for (int h = 0; h < 2; h++) {
                const int r = rw + mt * 16 + h * 8;
                const float v0 = alpha * acc[mt][nt][h * 2 + 0];
                const float v1 = alpha * acc[mt][nt][h * 2 + 1];
                const long long ci = bz * sC + (long long)r * ldc + cc;
                if (OUTBF) {
                    const __nv_bfloat16 h0 = __float2bfloat16(v0);
                    const __nv_bfloat16 h1 = __float2bfloat16(v1);
                    ushort2 H, L;
                    H.x = __bfloat16_as_ushort(h0);
                    H.y = __bfloat16_as_ushort(h1);
                    L.x = __bfloat16_as_ushort(__float2bfloat16(v0 - __bfloat162float(h0)));
                    L.y = __bfloat16_as_ushort(__float2bfloat16(v1 - __bfloat162float(h1)));
                    *(ushort2*)&Chi[ci] = H;
                    *(ushort2*)&Clo[ci] = L;
                } else {
                    float2 o; o.x = v0; o.y = v1;
                    *(float2*)&C[ci] = o;
                }
            }
        }
}

// ---------------------------------------------------------------------------
// fp32 -> bf16 hi/lo split (vectorized)
// ---------------------------------------------------------------------------
__global__ void __launch_bounds__(256) split_k(
    const float* __restrict__ in, __nv_bfloat16* __restrict__ hi,
    __nv_bfloat16* __restrict__ lo, long long n4)
{
    long long i = blockIdx.x * (long long)blockDim.x + threadIdx.x;
    const long long stride = (long long)gridDim.x * blockDim.x;
    const float4* in4 = (const float4*)in;
    ushort4* h4 = (ushort4*)hi;
    ushort4* l4 = (ushort4*)lo;
    for (; i < n4; i += stride) {
        const float4 v = in4[i];
        const __nv_bfloat16 a = __float2bfloat16(v.x);
        const __nv_bfloat16 b = __float2bfloat16(v.y);
        const __nv_bfloat16 c = __float2bfloat16(v.z);
        const __nv_bfloat16 d = __float2bfloat16(v.w);
        ushort4 H;
        H.x = __bfloat16_as_ushort(a); H.y = __bfloat16_as_ushort(b);
        H.z = __bfloat16_as_ushort(c); H.w = __bfloat16_as_ushort(d);
        ushort4 L;
        L.x = __bfloat16_as_ushort(__float2bfloat16(v.x - __bfloat162float(a)));
        L.y = __bfloat16_as_ushort(__float2bfloat16(v.y - __bfloat162float(b)));
        L.z = __bfloat16_as_ushort(__float2bfloat16(v.z - __bfloat162float(c)));
        L.w = __bfloat16_as_ushort(__float2bfloat16(v.w - __bfloat162float(d)));
        h4[i] = H;
        l4[i] = L;
    }
}

// ---------------------------------------------------------------------------
// Row softmax over TT=2048 cols; output split to bf16 hi/lo.
// ---------------------------------------------------------------------------
__global__ void __launch_bounds__(256) softmax_split(
    const float* __restrict__ S, __nv_bfloat16* __restrict__ Phi,
    __nv_bfloat16* __restrict__ Plo)
{
    __shared__ float red[8];
    const float* p = S + (long long)blockIdx.x * TT;
    const int tid = threadIdx.x;

    float vals[8];
    float m = -3.4e38f;
#pragma unroll
    for (int i = 0; i < 8; ++i) {
        vals[i] = p[tid + 256 * i];
        m = fmaxf(m, vals[i]);
    }
#pragma unroll
    for (int o = 16; o > 0; o >>= 1) m = fmaxf(m, __shfl_xor_sync(0xffffffffu, m, o));
    if ((tid & 31) == 0) red[tid >> 5] = m;
    __syncthreads();
    float M = red[0];
#pragma unroll
    for (int i = 1; i < 8; ++i) M = fmaxf(M, red[i]);

    float s = 0.0f;
#pragma unroll
    for (int i = 0; i < 8; ++i) { vals[i] = __expf(vals[i] - M); s += vals[i]; }
#pragma unroll
    for (int o = 16; o > 0; o >>= 1) s += __shfl_xor_sync(0xffffffffu, s, o);
    __syncthreads();
    if ((tid & 31) == 0) red[tid >> 5] = s;
    __syncthreads();
    float tot = red[0];
#pragma unroll
    for (int i = 1; i < 8; ++i) tot += red[i];

    const float inv = 1.0f / tot;
    __nv_bfloat16* ph = Phi + (long long)blockIdx.x * TT;
    __nv_bfloat16* pl = Plo + (long long)blockIdx.x * TT;
#pragma unroll
    for (int i = 0; i < 8; ++i) {
        const float v = vals[i] * inv;
        const __nv_bfloat16 h = __float2bfloat16(v);
        ph[tid + 256 * i] = h;
        pl[tid + 256 * i] = __float2bfloat16(v - __bfloat162float(h));
    }
}

// ---------------------------------------------------------------------------
// Launch sequence
// ---------------------------------------------------------------------------
extern "C" void kernel_launch(void* const* d_in, const int* in_sizes, int n_in,
                              void* d_out, int out_size)
{
    (void)in_sizes; (void)n_in; (void)out_size;
    const float* x  = (const float*)d_in[0];
    const float* Wq = (const float*)d_in[1];
    const float* Wk = (const float*)d_in[2];
    const float* Wv = (const float*)d_in[3];
    const float* Wo = (const float*)d_in[4];
    float* out = (float*)d_out;

    __nv_bfloat16 *xhi, *xlo, *wqhi, *wqlo, *wkhi, *wklo, *wvhi, *wvlo, *wohi, *wolo;
    __nv_bfloat16 *qhi, *qlo, *khi, *klo, *vthi, *vtlo, *phi, *plo, *ohi, *olo;
    float* S;
    cudaGetSymbolAddress((void**)&xhi, g_xhi);   cudaGetSymbolAddress((void**)&xlo, g_xlo);
    cudaGetSymbolAddress((void**)&wqhi, g_wqhi); cudaGetSymbolAddress((void**)&wqlo, g_wqlo);
    cudaGetSymbolAddress((void**)&wkhi, g_wkhi); cudaGetSymbolAddress((void**)&wklo, g_wklo);
    cudaGetSymbolAddress((void**)&wvhi, g_wvhi); cudaGetSymbolAddress((void**)&wvlo, g_wvlo);
    cudaGetSymbolAddress((void**)&wohi, g_wohi); cudaGetSymbolAddress((void**)&wolo, g_wolo);
    cudaGetSymbolAddress((void**)&qhi, g_qhi);   cudaGetSymbolAddress((void**)&qlo, g_qlo);
    cudaGetSymbolAddress((void**)&khi, g_khi);   cudaGetSymbolAddress((void**)&klo, g_klo);
    cudaGetSymbolAddress((void**)&vthi, g_vthi); cudaGetSymbolAddress((void**)&vtlo, g_vtlo);
    cudaGetSymbolAddress((void**)&phi, g_phi);   cudaGetSymbolAddress((void**)&plo, g_plo);
    cudaGetSymbolAddress((void**)&ohi, g_ohi);   cudaGetSymbolAddress((void**)&olo, g_olo);
    cudaGetSymbolAddress((void**)&S, g_s);

    cudaFuncSetAttribute(gemm_mma<0>, cudaFuncAttributeMaxDynamicSharedMemorySize, SMEM_TOTAL);
    cudaFuncSetAttribute(gemm_mma<1>, cudaFuncAttributeMaxDynamicSharedMemorySize, SMEM_TOTAL);

    const dim3 blk(512);
    const dim3 sblk(256);

    // 0) split inputs
    split_k<<<2048, sblk>>>(x,  xhi,  xlo,  (long long)MTOT * NXC / 4);
    split_k<<<256,  sblk>>>(Wq, wqhi, wqlo, (long long)NHC * NXC / 4);
    split_k<<<256,  sblk>>>(Wk, wkhi, wklo, (long long)NHC * NXC / 4);
    split_k<<<256,  sblk>>>(Wv, wvhi, wvlo, (long long)NHC * NXC / 4);
    split_k<<<256,  sblk>>>(Wo, wohi, wolo, (long long)NHC * NHC / 4);

    // 1) q = x @ Wq^T, k = x @ Wk^T   [16384 x 1024]
    {
        dim3 g(NHC / 128, MTOT / 256, 1);
        gemm_mma<1><<<g, blk, SMEM_TOTAL>>>(xhi, xlo, wqhi, wqlo,
                                            nullptr, qhi, qlo,
                                            NXC, NXC, NXC, NHC, 0, 0, 0, 1.0f);
        gemm_mma<1><<<g, blk, SMEM_TOTAL>>>(xhi, xlo, wkhi, wklo,
                                            nullptr, khi, klo,
                                            NXC, NXC, NXC, NHC, 0, 0, 0, 1.0f);
    }

    // 2) vT[h, b*T+t] = Wv @ x^T     [1024 x 16384]
    {
        dim3 g(MTOT / 128, NHC / 256, 1);
        gemm_mma<1><<<g, blk, SMEM_TOTAL>>>(wvhi, wvlo, xhi, xlo,
                                            nullptr, vthi, vtlo,
                                            NXC, NXC, NXC, MTOT, 0, 0, 0, 1.0f);
    }

    // 3) scores: S_b = (q_b @ k_b^T) / sqrt(T)   [2048 x 2048] x 8
    {
        dim3 g(TT / 128, TT / 256, BB);
        gemm_mma<0><<<g, blk, SMEM_TOTAL>>>(qhi, qlo, khi, klo,
                                            S, nullptr, nullptr,
                                            NHC, NHC, NHC, TT,
                                            (long long)TT * NHC, (long long)TT * NHC,
                                            (long long)TT * TT, 0.022097086912079608f);
    }

    // 4) softmax rows -> P (bf16 split)
    softmax_split<<<BB * TT, sblk>>>(S, phi, plo);

    // 5) o_b = P_b @ vT_b^T          [2048 x 1024] x 8
    {
        dim3 g(NHC / 128, TT / 256, BB);
        gemm_mma<1><<<g, blk, SMEM_TOTAL>>>(phi, plo, vthi, vtlo,
                                            nullptr, ohi, olo,
                                            TT, TT, MTOT, NHC,
                                            (long long)TT * TT, (long long)TT,
                                            (long long)TT * NHC, 1.0f);
    }

    // 6) out = o @ Wo^T              [16384 x 1024]
    {
        dim3 g(NHC / 128, MTOT / 256, 1);
        gemm_mma<0><<<g, blk, SMEM_TOTAL>>>(ohi, olo, wohi, wolo,
                                            out, nullptr, nullptr,
                                            NHC, NHC, NHC, NHC, 0, 0, 0, 1.0f);
    }
}

// round 6
// speedup vs baseline: 1.1171x; 1.1171x over previous
#include <cuda_runtime.h>
#include <cuda_bf16.h>
#include <cstdint>

#define BB   8
#define TT   2048
#define NXC  1024
#define NHC  1024
#define MTOT (BB * TT)   // 16384

// ---------------------------------------------------------------------------
// Scratch (device globals — no allocation allowed anywhere)
// ---------------------------------------------------------------------------
__device__ __nv_bfloat16 g_xhi[(size_t)MTOT * NXC], g_xlo[(size_t)MTOT * NXC];
__device__ __nv_bfloat16 g_wqhi[NHC * NXC], g_wqlo[NHC * NXC];
__device__ __nv_bfloat16 g_wkhi[NHC * NXC], g_wklo[NHC * NXC];
__device__ __nv_bfloat16 g_wvhi[NHC * NXC], g_wvlo[NHC * NXC];
__device__ __nv_bfloat16 g_wohi[NHC * NHC], g_wolo[NHC * NHC];
__device__ __nv_bfloat16 g_qhi[(size_t)MTOT * NHC], g_qlo[(size_t)MTOT * NHC];
__device__ __nv_bfloat16 g_khi[(size_t)MTOT * NHC], g_klo[(size_t)MTOT * NHC];
__device__ __nv_bfloat16 g_vthi[(size_t)NHC * MTOT], g_vtlo[(size_t)NHC * MTOT];
__device__ float         g_s[(size_t)BB * TT * TT];
__device__ __nv_bfloat16 g_phi[(size_t)BB * TT * TT], g_plo[(size_t)BB * TT * TT];
__device__ __nv_bfloat16 g_ohi[(size_t)MTOT * NHC], g_olo[(size_t)MTOT * NHC];

// ---------------------------------------------------------------------------
// PTX helpers (sm_80-era only — must be valid under compute_103 virtual arch)
// ---------------------------------------------------------------------------
__device__ __forceinline__ uint32_t smem_u32(const void* p) {
    uint32_t a;
    asm("{ .reg .u64 t; cvta.to.shared.u64 t, %1; cvt.u32.u64 %0, t; }"
        : "=r"(a) : "l"(p));
    return a;
}
__device__ __forceinline__ void cpa16(uint32_t dst, const void* src) {
    asm volatile("cp.async.cg.shared.global [%0], [%1], 16;\n" :: "r"(dst), "l"(src));
}
__device__ __forceinline__ void cpa_commit() {
    asm volatile("cp.async.commit_group;\n" ::: "memory");
}
template <int N>
__device__ __forceinline__ void cpa_wait() {
    asm volatile("cp.async.wait_group %0;\n" :: "n"(N) : "memory");
}
__device__ __forceinline__ void ldsm4(uint32_t* r, uint32_t addr) {
    asm volatile("ldmatrix.sync.aligned.m8n8.x4.shared.b16 {%0,%1,%2,%3}, [%4];"
                 : "=r"(r[0]), "=r"(r[1]), "=r"(r[2]), "=r"(r[3]) : "r"(addr));
}
__device__ __forceinline__ void mma16816(float* d, const uint32_t* a, const uint32_t* b) {
    asm volatile(
        "mma.sync.aligned.m16n8k16.row.col.f32.bf16.bf16.f32 "
        "{%0,%1,%2,%3}, {%4,%5,%6,%7}, {%8,%9}, {%0,%1,%2,%3};"
        : "+f"(d[0]), "+f"(d[1]), "+f"(d[2]), "+f"(d[3])
        : "r"(a[0]), "r"(a[1]), "r"(a[2]), "r"(a[3]), "r"(b[0]), "r"(b[1]));
}
// SW64 swizzle for 64-byte rows (K-chunk = 32 bf16)
__device__ __forceinline__ uint32_t swz64(uint32_t off) {
    return off ^ ((off >> 3) & 0x30);
}

// ---------------------------------------------------------------------------
// mma.sync NT GEMM:  C[M,N] = alpha * (A[M,K] @ B[N,K]^T)
// A = Ahi + Alo, B = Bhi + Blo (bf16 split); fp32 accumulate; 3-term product.
// Tile: 128x128, 8 warps (4 x 2), warp tile 32x64, K chunks of 32 bf16.
// 2-stage cp.async, 32 KB/stage -> 64 KB/CTA -> 2 CTAs/SM for cross-CTA
// latency hiding. grid = (N/128, M/128, batch). OUTBF=1: bf16 hi/lo out.
// ---------------------------------------------------------------------------
#define A_HI 0
#define A_LO 8192
#define B_HI 16384
#define B_LO 24576
#define STG  32768                    // 32 KB per stage
#define SMEM_TOTAL (2 * STG)          // 64 KB per CTA

template <int OUTBF>
__global__ void __launch_bounds__(256, 2) gemm_mma(
    const __nv_bfloat16* __restrict__ Ahi, const __nv_bfloat16* __restrict__ Alo,
    const __nv_bfloat16* __restrict__ Bhi, const __nv_bfloat16* __restrict__ Blo,
    float* __restrict__ C, __nv_bfloat16* __restrict__ Chi, __nv_bfloat16* __restrict__ Clo,
    int K, int lda, int ldb, int ldc,
    long long sA, long long sB, long long sC, float alpha)
{
    extern __shared__ __align__(1024) char smem[];
    const uint32_t sbase = smem_u32(smem);
    const int tid = threadIdx.x;
    const int wid = tid >> 5, lane = tid & 31;
    const long long bz = blockIdx.z;
    const int row0 = blockIdx.y * 128;
    const int col0 = blockIdx.x * 128;

    const char* gAhi = (const char*)(Ahi + bz * sA + (long long)row0 * lda);
    const char* gAlo = (const char*)(Alo + bz * sA + (long long)row0 * lda);
    const char* gBhi = (const char*)(Bhi + bz * sB + (long long)col0 * ldb);
    const char* gBlo = (const char*)(Blo + bz * sB + (long long)col0 * ldb);
    const long long ldab = (long long)lda * 2;
    const long long ldbb = (long long)ldb * 2;

    // Stage-load addressing: 128 rows x 64 B per buffer; 512 x 16B chunks,
    // 2 per thread per buffer.
    auto load_stage = [&](int c) {
        const uint32_t sb = sbase + ((c & 1) ? (uint32_t)STG : 0u);
        const long long kb = (long long)c * 64;         // 32 bf16 = 64 B
#pragma unroll
        for (int i = 0; i < 2; i++) {
            const uint32_t idx = (uint32_t)tid + (uint32_t)(i << 8);  // 0..511
            const uint32_t r  = idx >> 2;               // 0..127
            const uint32_t cb = (idx & 3) << 4;         // 0,16,32,48
            const uint32_t off = swz64((r << 6) + cb);
            const long long ga = (long long)r * ldab + kb + cb;
            const long long gb = (long long)r * ldbb + kb + cb;
            cpa16(sb + A_HI + off, gAhi + ga);
            cpa16(sb + A_LO + off, gAlo + ga);
            cpa16(sb + B_HI + off, gBhi + gb);
            cpa16(sb + B_LO + off, gBlo + gb);
        }
        cpa_commit();
    };

    const int NC = K >> 5;            // chunks of 32
    const int warp_m = wid & 3;       // 4 warps down M (32 rows each)
    const int warp_n = wid >> 2;      // 2 warps across N (64 cols each)
    const int lrow = lane & 15;
    const uint32_t klane = (lane >> 4) << 4;

    float acc[2][8][4];
#pragma unroll
    for (int i = 0; i < 2; i++)
#pragma unroll
        for (int j = 0; j < 8; j++)
#pragma unroll
            for (int k = 0; k < 4; k++) acc[i][j][k] = 0.0f;

    load_stage(0);

    for (int c = 0; c < NC; c++) {
        if (c + 1 < NC) { load_stage(c + 1); cpa_wait<1>(); }
        else            { cpa_wait<0>(); }
        __syncthreads();

        const uint32_t sb = sbase + ((c & 1) ? (uint32_t)STG : 0u);
#pragma unroll
        for (int ks = 0; ks < 2; ks++) {
            const uint32_t kbyte = (ks << 5) + klane;
            uint32_t ah[2][4], al[2][4];
#pragma unroll
            for (int mt = 0; mt < 2; mt++) {
                const uint32_t off =
                    swz64((uint32_t)((warp_m * 32 + mt * 16 + lrow) << 6) + kbyte);
                ldsm4(ah[mt], sb + A_HI + off);
                ldsm4(al[mt], sb + A_LO + off);
            }
            uint32_t bh[4][4], bl[4][4];
#pragma unroll
            for (int ng = 0; ng < 4; ng++) {
                const uint32_t off =
                    swz64((uint32_t)((warp_n * 64 + ng * 16 + lrow) << 6) + kbyte);
                ldsm4(bh[ng], sb + B_HI + off);
                ldsm4(bl[ng], sb + B_LO + off);
            }
#pragma unroll
            for (int mt = 0; mt < 2; mt++)
#pragma unroll
                for (int nt = 0; nt < 8; nt++) {
                    const int ng = nt >> 1, j = nt & 1;
                    uint32_t B0[2] = { bh[ng][j], bh[ng][j + 2] };
                    uint32_t L0[2] = { bl[ng][j], bl[ng][j + 2] };
                    mma16816(acc[mt][nt], ah[mt], B0);   // hi*hi
                    mma16816(acc[mt][nt], al[mt], B0);   // lo*hi
                    mma16816(acc[mt][nt], ah[mt], L0);   // hi*lo
                }
        }
        __syncthreads();
    }

    // Epilogue: c-frag rows lane/4 (+8), cols 2*(lane%4)+1
    const int rw = row0 + warp_m * 32 + (lane >> 2);
    const int cw = col0 + warp_n * 64 + (lane & 3) * 2;
#pragma unroll
    for (int mt = 0; mt < 2; mt++)
#pragma unroll
        for (int nt = 0; nt < 8; nt++) {
            const int cc = cw + nt * 8;
#pragma unroll
            for (int h = 0; h < 2; h++) {
                const int r = rw + mt * 16 + h * 8;
                const float v0 = alpha * acc[mt][nt][h * 2 + 0];
                const float v1 = alpha * acc[mt][nt][h * 2 + 1];
                const long long ci = bz * sC + (long long)r * ldc + cc;
                if (OUTBF) {
                    const __nv_bfloat16 h0 = __float2bfloat16(v0);
                    const __nv_bfloat16 h1 = __float2bfloat16(v1);
                    ushort2 H, L;
                    H.x = __bfloat16_as_ushort(h0);
                    H.y = __bfloat16_as_ushort(h1);
                    L.x = __bfloat16_as_ushort(__float2bfloat16(v0 - __bfloat162float(h0)));
                    L.y = __bfloat16_as_ushort(__float2bfloat16(v1 - __bfloat162float(h1)));
                    *(ushort2*)&Chi[ci] = H;
                    *(ushort2*)&Clo[ci] = L;
                } else {
                    float2 o; o.x = v0; o.y = v1;
                    *(float2*)&C[ci] = o;
                }
            }
        }
}

// ---------------------------------------------------------------------------
// fp32 -> bf16 hi/lo split (vectorized)
// ---------------------------------------------------------------------------
__global__ void __launch_bounds__(256) split_k(
    const float* __restrict__ in, __nv_bfloat16* __restrict__ hi,
    __nv_bfloat16* __restrict__ lo, long long n4)
{
    long long i = blockIdx.x * (long long)blockDim.x + threadIdx.x;
    const long long stride = (long long)gridDim.x * blockDim.x;
    const float4* in4 = (const float4*)in;
    ushort4* h4 = (ushort4*)hi;
    ushort4* l4 = (ushort4*)lo;
    for (; i < n4; i += stride) {
        const float4 v = in4[i];
        const __nv_bfloat16 a = __float2bfloat16(v.x);
        const __nv_bfloat16 b = __float2bfloat16(v.y);
        const __nv_bfloat16 c = __float2bfloat16(v.z);
        const __nv_bfloat16 d = __float2bfloat16(v.w);
        ushort4 H;
        H.x = __bfloat16_as_ushort(a); H.y = __bfloat16_as_ushort(b);
        H.z = __bfloat16_as_ushort(c); H.w = __bfloat16_as_ushort(d);
        ushort4 L;
        L.x = __bfloat16_as_ushort(__float2bfloat16(v.x - __bfloat162float(a)));
        L.y = __bfloat16_as_ushort(__float2bfloat16(v.y - __bfloat162float(b)));
        L.z = __bfloat16_as_ushort(__float2bfloat16(v.z - __bfloat162float(c)));
        L.w = __bfloat16_as_ushort(__float2bfloat16(v.w - __bfloat162float(d)));
        h4[i] = H;
        l4[i] = L;
    }
}

// ---------------------------------------------------------------------------
// Row softmax over TT=2048 cols; output split to bf16 hi/lo.
// ---------------------------------------------------------------------------
__global__ void __launch_bounds__(256) softmax_split(
    const float* __restrict__ S, __nv_bfloat16* __restrict__ Phi,
    __nv_bfloat16* __restrict__ Plo)
{
    __shared__ float red[8];
    const float* p = S + (long long)blockIdx.x * TT;
    const int tid = threadIdx.x;

    float vals[8];
    float m = -3.4e38f;
#pragma unroll
    for (int i = 0; i < 8; ++i) {
        vals[i] = p[tid + 256 * i];
        m = fmaxf(m, vals[i]);
    }
#pragma unroll
    for (int o = 16; o > 0; o >>= 1) m = fmaxf(m, __shfl_xor_sync(0xffffffffu, m, o));
    if ((tid & 31) == 0) red[tid >> 5] = m;
    __syncthreads();
    float M = red[0];
#pragma unroll
    for (int i = 1; i < 8; ++i) M = fmaxf(M, red[i]);

    float s = 0.0f;
#pragma unroll
    for (int i = 0; i < 8; ++i) { vals[i] = __expf(vals[i] - M); s += vals[i]; }
#pragma unroll
    for (int o = 16; o > 0; o >>= 1) s += __shfl_xor_sync(0xffffffffu, s, o);
    __syncthreads();
    if ((tid & 31) == 0) red[tid >> 5] = s;
    __syncthreads();
    float tot = red[0];
#pragma unroll
    for (int i = 1; i < 8; ++i) tot += red[i];

    const float inv = 1.0f / tot;
    __nv_bfloat16* ph = Phi + (long long)blockIdx.x * TT;
    __nv_bfloat16* pl = Plo + (long long)blockIdx.x * TT;
#pragma unroll
    for (int i = 0; i < 8; ++i) {
        const float v = vals[i] * inv;
        const __nv_bfloat16 h = __float2bfloat16(v);
        ph[tid + 256 * i] = h;
        pl[tid + 256 * i] = __float2bfloat16(v - __bfloat162float(h));
    }
}

// ---------------------------------------------------------------------------
// Launch sequence
// ---------------------------------------------------------------------------
extern "C" void kernel_launch(void* const* d_in, const int* in_sizes, int n_in,
                              void* d_out, int out_size)
{
    (void)in_sizes; (void)n_in; (void)out_size;
    const float* x  = (const float*)d_in[0];
    const float* Wq = (const float*)d_in[1];
    const float* Wk = (const float*)d_in[2];
    const float* Wv = (const float*)d_in[3];
    const float* Wo = (const float*)d_in[4];
    float* out = (float*)d_out;

    __nv_bfloat16 *xhi, *xlo, *wqhi, *wqlo, *wkhi, *wklo, *wvhi, *wvlo, *wohi, *wolo;
    __nv_bfloat16 *qhi, *qlo, *khi, *klo, *vthi, *vtlo, *phi, *plo, *ohi, *olo;
    float* S;
    cudaGetSymbolAddress((void**)&xhi, g_xhi);   cudaGetSymbolAddress((void**)&xlo, g_xlo);
    cudaGetSymbolAddress((void**)&wqhi, g_wqhi); cudaGetSymbolAddress((void**)&wqlo, g_wqlo);
    cudaGetSymbolAddress((void**)&wkhi, g_wkhi); cudaGetSymbolAddress((void**)&wklo, g_wklo);
    cudaGetSymbolAddress((void**)&wvhi, g_wvhi); cudaGetSymbolAddress((void**)&wvlo, g_wvlo);
    cudaGetSymbolAddress((void**)&wohi, g_wohi); cudaGetSymbolAddress((void**)&wolo, g_wolo);
    cudaGetSymbolAddress((void**)&qhi, g_qhi);   cudaGetSymbolAddress((void**)&qlo, g_qlo);
    cudaGetSymbolAddress((void**)&khi, g_khi);   cudaGetSymbolAddress((void**)&klo, g_klo);
    cudaGetSymbolAddress((void**)&vthi, g_vthi); cudaGetSymbolAddress((void**)&vtlo, g_vtlo);
    cudaGetSymbolAddress((void**)&phi, g_phi);   cudaGetSymbolAddress((void**)&plo, g_plo);
    cudaGetSymbolAddress((void**)&ohi, g_ohi);   cudaGetSymbolAddress((void**)&olo, g_olo);
    cudaGetSymbolAddress((void**)&S, g_s);

    cudaFuncSetAttribute(gemm_mma<0>, cudaFuncAttributeMaxDynamicSharedMemorySize, SMEM_TOTAL);
    cudaFuncSetAttribute(gemm_mma<1>, cudaFuncAttributeMaxDynamicSharedMemorySize, SMEM_TOTAL);

    const dim3 blk(256);

    // 0) split inputs
    split_k<<<2048, blk>>>(x,  xhi,  xlo,  (long long)MTOT * NXC / 4);
    split_k<<<256,  blk>>>(Wq, wqhi, wqlo, (long long)NHC * NXC / 4);
    split_k<<<256,  blk>>>(Wk, wkhi, wklo, (long long)NHC * NXC / 4);
    split_k<<<256,  blk>>>(Wv, wvhi, wvlo, (long long)NHC * NXC / 4);
    split_k<<<256,  blk>>>(Wo, wohi, wolo, (long long)NHC * NHC / 4);

    // 1) q = x @ Wq^T, k = x @ Wk^T   [16384 x 1024]
    {
        dim3 g(NHC / 128, MTOT / 128, 1);
        gemm_mma<1><<<g, blk, SMEM_TOTAL>>>(xhi, xlo, wqhi, wqlo,
                                            nullptr, qhi, qlo,
                                            NXC, NXC, NXC, NHC, 0, 0, 0, 1.0f);
        gemm_mma<1><<<g, blk, SMEM_TOTAL>>>(xhi, xlo, wkhi, wklo,
                                            nullptr, khi, klo,
                                            NXC, NXC, NXC, NHC, 0, 0, 0, 1.0f);
    }

    // 2) vT[h, b*T+t] = Wv @ x^T     [1024 x 16384]
    {
        dim3 g(MTOT / 128, NHC / 128, 1);
        gemm_mma<1><<<g, blk, SMEM_TOTAL>>>(wvhi, wvlo, xhi, xlo,
                                            nullptr, vthi, vtlo,
                                            NXC, NXC, NXC, MTOT, 0, 0, 0, 1.0f);
    }

    // 3) scores: S_b = (q_b @ k_b^T) / sqrt(T)   [2048 x 2048] x 8
    {
        dim3 g(TT / 128, TT / 128, BB);
        gemm_mma<0><<<g, blk, SMEM_TOTAL>>>(qhi, qlo, khi, klo,
                                            S, nullptr, nullptr,
                                            NHC, NHC, NHC, TT,
                                            (long long)TT * NHC, (long long)TT * NHC,
                                            (long long)TT * TT, 0.022097086912079608f);
    }

    // 4) softmax rows -> P (bf16 split)
    softmax_split<<<BB * TT, blk>>>(S, phi, plo);

    // 5) o_b = P_b @ vT_b^T          [2048 x 1024] x 8
    {
        dim3 g(NHC / 128, TT / 128, BB);
        gemm_mma<1><<<g, blk, SMEM_TOTAL>>>(phi, plo, vthi, vtlo,
                                            nullptr, ohi, olo,
                                            TT, TT, MTOT, NHC,
                                            (long long)TT * TT, (long long)TT,
                                            (long long)TT * NHC, 1.0f);
    }

    // 6) out = o @ Wo^T              [16384 x 1024]
    {
        dim3 g(NHC / 128, MTOT / 128, 1);
        gemm_mma<0><<<g, blk, SMEM_TOTAL>>>(ohi, olo, wohi, wolo,
                                            out, nullptr, nullptr,
                                            NHC, NHC, NHC, NHC, 0, 0, 0, 1.0f);
    }
}

// round 7
// speedup vs baseline: 1.2027x; 1.0767x over previous
#include <cuda_runtime.h>
#include <cuda_fp16.h>
#include <cstdint>

#define BB   8
#define TT   2048
#define NXC  1024
#define NHC  1024
#define MTOT (BB * TT)   // 16384

// ---------------------------------------------------------------------------
// Scratch (device globals — no allocation allowed anywhere)
// ---------------------------------------------------------------------------
__device__ __half g_xhi[(size_t)MTOT * NXC], g_xlo[(size_t)MTOT * NXC];
__device__ __half g_wqhi[NHC * NXC], g_wqlo[NHC * NXC];
__device__ __half g_wkhi[NHC * NXC], g_wklo[NHC * NXC];
__device__ __half g_wvhi[NHC * NXC], g_wvlo[NHC * NXC];
__device__ __half g_wohi[NHC * NHC], g_wolo[NHC * NHC];
__device__ __half g_qhi[(size_t)MTOT * NHC], g_qlo[(size_t)MTOT * NHC];
__device__ __half g_khi[(size_t)MTOT * NHC], g_klo[(size_t)MTOT * NHC];
__device__ __half g_vthi[(size_t)NHC * MTOT], g_vtlo[(size_t)NHC * MTOT];
__device__ float  g_s[(size_t)BB * TT * TT];
__device__ __half g_phi[(size_t)BB * TT * TT], g_plo[(size_t)BB * TT * TT];
__device__ __half g_ohi[(size_t)MTOT * NHC], g_olo[(size_t)MTOT * NHC];

// ---------------------------------------------------------------------------
// PTX helpers (sm_80-era only — must be valid under compute_103 virtual arch)
// ---------------------------------------------------------------------------
__device__ __forceinline__ uint32_t smem_u32(const void* p) {
    uint32_t a;
    asm("{ .reg .u64 t; cvta.to.shared.u64 t, %1; cvt.u32.u64 %0, t; }"
        : "=r"(a) : "l"(p));
    return a;
}
__device__ __forceinline__ void cpa16(uint32_t dst, const void* src) {
    asm volatile("cp.async.cg.shared.global [%0], [%1], 16;\n" :: "r"(dst), "l"(src));
}
__device__ __forceinline__ void cpa_commit() {
    asm volatile("cp.async.commit_group;\n" ::: "memory");
}
template <int N>
__device__ __forceinline__ void cpa_wait() {
    asm volatile("cp.async.wait_group %0;\n" :: "n"(N) : "memory");
}
__device__ __forceinline__ void ldsm4(uint32_t* r, uint32_t addr) {
    asm volatile("ldmatrix.sync.aligned.m8n8.x4.shared.b16 {%0,%1,%2,%3}, [%4];"
                 : "=r"(r[0]), "=r"(r[1]), "=r"(r[2]), "=r"(r[3]) : "r"(addr));
}
// fp16 inputs, fp32 accumulate
__device__ __forceinline__ void mma16816(float* d, const uint32_t* a, const uint32_t* b) {
    asm volatile(
        "mma.sync.aligned.m16n8k16.row.col.f32.f16.f16.f32 "
        "{%0,%1,%2,%3}, {%4,%5,%6,%7}, {%8,%9}, {%0,%1,%2,%3};"
        : "+f"(d[0]), "+f"(d[1]), "+f"(d[2]), "+f"(d[3])
        : "r"(a[0]), "r"(a[1]), "r"(a[2]), "r"(a[3]), "r"(b[0]), "r"(b[1]));
}
__device__ __forceinline__ uint32_t swz(uint32_t off) {
    return off ^ ((off >> 3) & 0x70);
}

// ---------------------------------------------------------------------------
// mma.sync NT GEMM:  C[M,N] = alpha * (A[M,K] @ B[N,K]^T)
// A = Ahi + Alo, B = Bhi + Blo (fp16 split); fp32 accumulate.
// NTERMS=3: AhBh + AlBh + AhBl (fp32-class).  NTERMS=2: AhBh + AlBh
// (= A·Bh; error ~2^-11 — used only where downstream slack exists).
// Tile: 128x128, 8 warps (4 x 2), warp tile 32x64, K chunks of 64 fp16.
// grid = (N/128, M/128, batch). OUTH=1: write fp16 hi/lo; else fp32.
// ---------------------------------------------------------------------------
#define STG 65536                     // Ahi 16K | Alo 16K | Bhi 16K | Blo 16K
#define SMEM_TOTAL (2 * STG)          // 128 KB, double-buffered

template <int OUTH, int NTERMS>
__global__ void __launch_bounds__(256, 1) gemm_mma(
    const __half* __restrict__ Ahi, const __half* __restrict__ Alo,
    const __half* __restrict__ Bhi, const __half* __restrict__ Blo,
    float* __restrict__ C, __half* __restrict__ Chi, __half* __restrict__ Clo,
    int K, int lda, int ldb, int ldc,
    long long sA, long long sB, long long sC, float alpha)
{
    extern __shared__ __align__(1024) char smem[];
    const uint32_t sbase = smem_u32(smem);
    const int tid = threadIdx.x;
    const int wid = tid >> 5, lane = tid & 31;
    const long long bz = blockIdx.z;
    const int row0 = blockIdx.y * 128;
    const int col0 = blockIdx.x * 128;

    const char* gAhi = (const char*)(Ahi + bz * sA + (long long)row0 * lda);
    const char* gAlo = (const char*)(Alo + bz * sA + (long long)row0 * lda);
    const char* gBhi = (const char*)(Bhi + bz * sB + (long long)col0 * ldb);
    const char* gBlo = (const char*)(Blo + bz * sB + (long long)col0 * ldb);
    const long long ldab = (long long)lda * 2;
    const long long ldbb = (long long)ldb * 2;

    auto load_stage = [&](int c) {
        const uint32_t sb = sbase + ((c & 1) ? (uint32_t)STG : 0u);
        const long long kb = (long long)c * 128;    // 64 fp16 = 128 B per chunk
#pragma unroll
        for (int i = 0; i < 4; i++) {
            const int id = tid + (i << 8);          // 0..1023
            const uint32_t r = id >> 3, cb = (id & 7) << 4;
            const uint32_t off = swz((r << 7) + cb);
            const long long ga = (long long)r * ldab + kb + cb;
            const long long gb = (long long)r * ldbb + kb + cb;
            cpa16(sb + off,          gAhi + ga);
            cpa16(sb + 16384 + off,  gAlo + ga);
            cpa16(sb + 32768 + off,  gBhi + gb);
            if (NTERMS == 3) cpa16(sb + 49152 + off, gBlo + gb);
        }
        cpa_commit();
    };

    const int NC = K >> 6;
    const int warp_m = wid & 3;       // 4 warps down M (32 rows each)
    const int warp_n = wid >> 2;      // 2 warps across N (64 cols each)
    const int lrow = lane & 15;
    const uint32_t klane = (lane >> 4) << 4;

    float acc[2][8][4];
#pragma unroll
    for (int i = 0; i < 2; i++)
#pragma unroll
        for (int j = 0; j < 8; j++)
#pragma unroll
            for (int k = 0; k < 4; k++) acc[i][j][k] = 0.0f;

    load_stage(0);

    for (int c = 0; c < NC; c++) {
        if (c + 1 < NC) { load_stage(c + 1); cpa_wait<1>(); }
        else            { cpa_wait<0>(); }
        __syncthreads();

        const uint32_t sb = sbase + ((c & 1) ? (uint32_t)STG : 0u);
#pragma unroll
        for (int ks = 0; ks < 4; ks++) {
            const uint32_t kbyte = (ks << 5) + klane;
            uint32_t ah[2][4], al[2][4];
#pragma unroll
            for (int mt = 0; mt < 2; mt++) {
                const uint32_t off =
                    swz((uint32_t)((warp_m * 32 + mt * 16 + lrow) << 7) + kbyte);
                ldsm4(ah[mt], sb + off);
                ldsm4(al[mt], sb + 16384 + off);
            }
            uint32_t bh[4][4], bl[4][4];
#pragma unroll
            for (int ng = 0; ng < 4; ng++) {
                const uint32_t off =
                    swz((uint32_t)((warp_n * 64 + ng * 16 + lrow) << 7) + kbyte);
                ldsm4(bh[ng], sb + 32768 + off);
                if (NTERMS == 3) ldsm4(bl[ng], sb + 49152 + off);
            }
#pragma unroll
            for (int mt = 0; mt < 2; mt++)
#pragma unroll
                for (int nt = 0; nt < 8; nt++) {
                    const int ng = nt >> 1, j = nt & 1;
                    uint32_t B0[2] = { bh[ng][j], bh[ng][j + 2] };
                    mma16816(acc[mt][nt], ah[mt], B0);       // hi*hi
                    mma16816(acc[mt][nt], al[mt], B0);       // lo*hi
                    if (NTERMS == 3) {
                        uint32_t L0[2] = { bl[ng][j], bl[ng][j + 2] };
                        mma16816(acc[mt][nt], ah[mt], L0);   // hi*lo
                    }
                }
        }
        __syncthreads();
    }

    // Epilogue: c-frag rows lane/4 (+8), cols 2*(lane%4)+1
    const int rw = row0 + warp_m * 32 + (lane >> 2);
    const int cw = col0 + warp_n * 64 + (lane & 3) * 2;
#pragma unroll
    for (int mt = 0; mt < 2; mt++)
#pragma unroll
        for (int nt = 0; nt < 8; nt++) {
            const int cc = cw + nt * 8;
#pragma unroll
            for (int h = 0; h < 2; h++) {
                const int r = rw + mt * 16 + h * 8;
                const float v0 = alpha * acc[mt][nt][h * 2 + 0];
                const float v1 = alpha * acc[mt][nt][h * 2 + 1];
                const long long ci = bz * sC + (long long)r * ldc + cc;
                if (OUTH) {
                    const __half h0 = __float2half(v0);
                    const __half h1 = __float2half(v1);
                    ushort2 H, L;
                    H.x = __half_as_ushort(h0);
                    H.y = __half_as_ushort(h1);
                    L.x = __half_as_ushort(__float2half(v0 - __half2float(h0)));
                    L.y = __half_as_ushort(__float2half(v1 - __half2float(h1)));
                    *(ushort2*)&Chi[ci] = H;
                    *(ushort2*)&Clo[ci] = L;
                } else {
                    float2 o; o.x = v0; o.y = v1;
                    *(float2*)&C[ci] = o;
                }
            }
        }
}

// ---------------------------------------------------------------------------
// Fused fp32 -> fp16 hi/lo split of x + all 4 weights in ONE launch.
// Blocks [0,2048): x.  [2048,2304): Wq.  [2304,2560): Wk.
// [2560,2816): Wv.  [2816,3072): Wo.
// ---------------------------------------------------------------------------
__device__ __forceinline__ void split4(const float4 v, ushort4& H, ushort4& L) {
    const __half a = __float2half(v.x), b = __float2half(v.y);
    const __half c = __float2half(v.z), d = __float2half(v.w);
    H.x = __half_as_ushort(a); H.y = __half_as_ushort(b);
    H.z = __half_as_ushort(c); H.w = __half_as_ushort(d);
    L.x = __half_as_ushort(__float2half(v.x - __half2float(a)));
    L.y = __half_as_ushort(__float2half(v.y - __half2float(b)));
    L.z = __half_as_ushort(__float2half(v.z - __half2float(c)));
    L.w = __half_as_ushort(__float2half(v.w - __half2float(d)));
}

__global__ void __launch_bounds__(256) split_all(
    const float* __restrict__ x,  const float* __restrict__ Wq,
    const float* __restrict__ Wk, const float* __restrict__ Wv,
    const float* __restrict__ Wo,
    __half* __restrict__ xhi,  __half* __restrict__ xlo,
    __half* __restrict__ wqhi, __half* __restrict__ wqlo,
    __half* __restrict__ wkhi, __half* __restrict__ wklo,
    __half* __restrict__ wvhi, __half* __restrict__ wvlo,
    __half* __restrict__ wohi, __half* __restrict__ wolo)
{
    const int b = blockIdx.x;
    const int tid = threadIdx.x;
    const float4* in4;
    ushort4 *h4, *l4;
    long long n4, i0, stride;
    if (b < 2048) {
        in4 = (const float4*)x;  h4 = (ushort4*)xhi;  l4 = (ushort4*)xlo;
        n4 = (long long)MTOT * NXC / 4;  i0 = (long long)b * 256 + tid;  stride = 2048 * 256;
    } else {
        const int w = (b - 2048) >> 8;          // 0..3
        const int lb = (b - 2048) & 255;        // 0..255
        const float* W[4] = {Wq, Wk, Wv, Wo};
        __half* WH[4] = {wqhi, wkhi, wvhi, wohi};
        __half* WL[4] = {wqlo, wklo, wvlo, wolo};
        in4 = (const float4*)W[w];  h4 = (ushort4*)WH[w];  l4 = (ushort4*)WL[w];
        n4 = (long long)NHC * NXC / 4;  i0 = (long long)lb * 256 + tid;  stride = 256 * 256;
    }
    for (long long i = i0; i < n4; i += stride) {
        ushort4 H, L;
        split4(in4[i], H, L);
        h4[i] = H;
        l4[i] = L;
    }
}

// ---------------------------------------------------------------------------
// Row softmax over TT=2048 cols; output split to fp16 hi/lo.
// ---------------------------------------------------------------------------
__global__ void __launch_bounds__(256) softmax_split(
    const float* __restrict__ S, __half* __restrict__ Phi,
    __half* __restrict__ Plo)
{
    __shared__ float red[8];
    const float* p = S + (long long)blockIdx.x * TT;
    const int tid = threadIdx.x;

    float vals[8];
    float m = -3.4e38f;
#pragma unroll
    for (int i = 0; i < 8; ++i) {
        vals[i] = p[tid + 256 * i];
        m = fmaxf(m, vals[i]);
    }
#pragma unroll
    for (int o = 16; o > 0; o >>= 1) m = fmaxf(m, __shfl_xor_sync(0xffffffffu, m, o));
    if ((tid & 31) == 0) red[tid >> 5] = m;
    __syncthreads();
    float M = red[0];
#pragma unroll
    for (int i = 1; i < 8; ++i) M = fmaxf(M, red[i]);

    float s = 0.0f;
#pragma unroll
    for (int i = 0; i < 8; ++i) { vals[i] = __expf(vals[i] - M); s += vals[i]; }
#pragma unroll
    for (int o = 16; o > 0; o >>= 1) s += __shfl_xor_sync(0xffffffffu, s, o);
    __syncthreads();
    if ((tid & 31) == 0) red[tid >> 5] = s;
    __syncthreads();
    float tot = red[0];
#pragma unroll
    for (int i = 1; i < 8; ++i) tot += red[i];

    const float inv = 1.0f / tot;
    __half* ph = Phi + (long long)blockIdx.x * TT;
    __half* pl = Plo + (long long)blockIdx.x * TT;
#pragma unroll
    for (int i = 0; i < 8; ++i) {
        const float v = vals[i] * inv;
        const __half h = __float2half(v);
        ph[tid + 256 * i] = h;
        pl[tid + 256 * i] = __float2half(v - __half2float(h));
    }
}

// ---------------------------------------------------------------------------
// Launch sequence.  Order matters for ncu (captures the 4th launch):
//   1 split_all, 2 q, 3 k, 4 SCORES, 5 v, 6 softmax, 7 pv, 8 out
// ---------------------------------------------------------------------------
extern "C" void kernel_launch(void* const* d_in, const int* in_sizes, int n_in,
                              void* d_out, int out_size)
{
    (void)in_sizes; (void)n_in; (void)out_size;
    const float* x  = (const float*)d_in[0];
    const float* Wq = (const float*)d_in[1];
    const float* Wk = (const float*)d_in[2];
    const float* Wv = (const float*)d_in[3];
    const float* Wo = (const float*)d_in[4];
    float* out = (float*)d_out;

    __half *xhi, *xlo, *wqhi, *wqlo, *wkhi, *wklo, *wvhi, *wvlo, *wohi, *wolo;
    __half *qhi, *qlo, *khi, *klo, *vthi, *vtlo, *phi, *plo, *ohi, *olo;
    float* S;
    cudaGetSymbolAddress((void**)&xhi, g_xhi);   cudaGetSymbolAddress((void**)&xlo, g_xlo);
    cudaGetSymbolAddress((void**)&wqhi, g_wqhi); cudaGetSymbolAddress((void**)&wqlo, g_wqlo);
    cudaGetSymbolAddress((void**)&wkhi, g_wkhi); cudaGetSymbolAddress((void**)&wklo, g_wklo);
    cudaGetSymbolAddress((void**)&wvhi, g_wvhi); cudaGetSymbolAddress((void**)&wvlo, g_wvlo);
    cudaGetSymbolAddress((void**)&wohi, g_wohi); cudaGetSymbolAddress((void**)&wolo, g_wolo);
    cudaGetSymbolAddress((void**)&qhi, g_qhi);   cudaGetSymbolAddress((void**)&qlo, g_qlo);
    cudaGetSymbolAddress((void**)&khi, g_khi);   cudaGetSymbolAddress((void**)&klo, g_klo);
    cudaGetSymbolAddress((void**)&vthi, g_vthi); cudaGetSymbolAddress((void**)&vtlo, g_vtlo);
    cudaGetSymbolAddress((void**)&phi, g_phi);   cudaGetSymbolAddress((void**)&plo, g_plo);
    cudaGetSymbolAddress((void**)&ohi, g_ohi);   cudaGetSymbolAddress((void**)&olo, g_olo);
    cudaGetSymbolAddress((void**)&S, g_s);

    cudaFuncSetAttribute(gemm_mma<0, 3>, cudaFuncAttributeMaxDynamicSharedMemorySize, SMEM_TOTAL);
    cudaFuncSetAttribute(gemm_mma<1, 3>, cudaFuncAttributeMaxDynamicSharedMemorySize, SMEM_TOTAL);
    cudaFuncSetAttribute(gemm_mma<0, 2>, cudaFuncAttributeMaxDynamicSharedMemorySize, SMEM_TOTAL);

    const dim3 blk(256);

    // 1) fused splits (one launch)
    split_all<<<3072, blk>>>(x, Wq, Wk, Wv, Wo,
                             xhi, xlo, wqhi, wqlo, wkhi, wklo,
                             wvhi, wvlo, wohi, wolo);

    // 2-3) q = x @ Wq^T, k = x @ Wk^T   [16384 x 1024], 3-term
    {
        dim3 g(NHC / 128, MTOT / 128, 1);
        gemm_mma<1, 3><<<g, blk, SMEM_TOTAL>>>(xhi, xlo, wqhi, wqlo,
                                               nullptr, qhi, qlo,
                                               NXC, NXC, NXC, NHC, 0, 0, 0, 1.0f);
        gemm_mma<1, 3><<<g, blk, SMEM_TOTAL>>>(xhi, xlo, wkhi, wklo,
                                               nullptr, khi, klo,
                                               NXC, NXC, NXC, NHC, 0, 0, 0, 1.0f);
    }

    // 4) scores: S_b = (q_b @ k_b^T)/sqrt(T), 2-term (A full, B hi only)
    {
        dim3 g(TT / 128, TT / 128, BB);
        gemm_mma<0, 2><<<g, blk, SMEM_TOTAL>>>(qhi, qlo, khi, klo,
                                               S, nullptr, nullptr,
                                               NHC, NHC, NHC, TT,
                                               (long long)TT * NHC, (long long)TT * NHC,
                                               (long long)TT * TT, 0.022097086912079608f);
    }

    // 5) vT[h, b*T+t] = Wv @ x^T     [1024 x 16384], 3-term
    {
        dim3 g(MTOT / 128, NHC / 128, 1);
        gemm_mma<1, 3><<<g, blk, SMEM_TOTAL>>>(wvhi, wvlo, xhi, xlo,
                                               nullptr, vthi, vtlo,
                                               NXC, NXC, NXC, MTOT, 0, 0, 0, 1.0f);
    }

    // 6) softmax rows -> P (fp16 split)
    softmax_split<<<BB * TT, blk>>>(S, phi, plo);

    // 7) o_b = P_b @ vT_b^T          [2048 x 1024] x 8, 3-term
    {
        dim3 g(NHC / 128, TT / 128, BB);
        gemm_mma<1, 3><<<g, blk, SMEM_TOTAL>>>(phi, plo, vthi, vtlo,
                                               nullptr, ohi, olo,
                                               TT, TT, MTOT, NHC,
                                               (long long)TT * TT, (long long)TT,
                                               (long long)TT * NHC, 1.0f);
    }

    // 8) out = o @ Wo^T              [16384 x 1024], 3-term
    {
        dim3 g(NHC / 128, MTOT / 128, 1);
        gemm_mma<0, 3><<<g, blk, SMEM_TOTAL>>>(ohi, olo, wohi, wolo,
                                               out, nullptr, nullptr,
                                               NHC, NHC, NHC, NHC, 0, 0, 0, 1.0f);
    }
}

// round 8
// speedup vs baseline: 1.3941x; 1.1591x over previous
#include <cuda_runtime.h>
#include <cuda_fp16.h>
#include <cstdint>

#define BB   8
#define TT   2048
#define NXC  1024
#define NHC  1024
#define MTOT (BB * TT)   // 16384

// ---------------------------------------------------------------------------
// Scratch (device globals — no allocation allowed anywhere)
// ---------------------------------------------------------------------------
__device__ __half g_xhi[(size_t)MTOT * NXC], g_xlo[(size_t)MTOT * NXC];
__device__ __half g_wqhi[NHC * NXC], g_wqlo[NHC * NXC];
__device__ __half g_wkhi[NHC * NXC], g_wklo[NHC * NXC];
__device__ __half g_wvhi[NHC * NXC], g_wvlo[NHC * NXC];
__device__ __half g_wohi[NHC * NHC], g_wolo[NHC * NHC];
__device__ __half g_qhi[(size_t)MTOT * NHC], g_qlo[(size_t)MTOT * NHC];
__device__ __half g_khi[(size_t)MTOT * NHC], g_klo[(size_t)MTOT * NHC];
__device__ __half g_vthi[(size_t)NHC * MTOT], g_vtlo[(size_t)NHC * MTOT];
__device__ float  g_s[(size_t)BB * TT * TT];
__device__ __half g_phi[(size_t)BB * TT * TT], g_plo[(size_t)BB * TT * TT];
__device__ __half g_ohi[(size_t)MTOT * NHC], g_olo[(size_t)MTOT * NHC];

// ---------------------------------------------------------------------------
// PTX helpers (sm_80-era only — must be valid under compute_103 virtual arch)
// ---------------------------------------------------------------------------
__device__ __forceinline__ uint32_t smem_u32(const void* p) {
    uint32_t a;
    asm("{ .reg .u64 t; cvta.to.shared.u64 t, %1; cvt.u32.u64 %0, t; }"
        : "=r"(a) : "l"(p));
    return a;
}
__device__ __forceinline__ void cpa16(uint32_t dst, const void* src) {
    asm volatile("cp.async.cg.shared.global [%0], [%1], 16;\n" :: "r"(dst), "l"(src));
}
__device__ __forceinline__ void cpa_commit() {
    asm volatile("cp.async.commit_group;\n" ::: "memory");
}
template <int N>
__device__ __forceinline__ void cpa_wait() {
    asm volatile("cp.async.wait_group %0;\n" :: "n"(N) : "memory");
}
__device__ __forceinline__ void ldsm4(uint32_t* r, uint32_t addr) {
    asm volatile("ldmatrix.sync.aligned.m8n8.x4.shared.b16 {%0,%1,%2,%3}, [%4];"
                 : "=r"(r[0]), "=r"(r[1]), "=r"(r[2]), "=r"(r[3]) : "r"(addr));
}
// fp16 inputs, fp32 accumulate
__device__ __forceinline__ void mma16816(float* d, const uint32_t* a, const uint32_t* b) {
    asm volatile(
        "mma.sync.aligned.m16n8k16.row.col.f32.f16.f16.f32 "
        "{%0,%1,%2,%3}, {%4,%5,%6,%7}, {%8,%9}, {%0,%1,%2,%3};"
        : "+f"(d[0]), "+f"(d[1]), "+f"(d[2]), "+f"(d[3])
        : "r"(a[0]), "r"(a[1]), "r"(a[2]), "r"(a[3]), "r"(b[0]), "r"(b[1]));
}
__device__ __forceinline__ uint32_t swz(uint32_t off) {
    return off ^ ((off >> 3) & 0x70);
}

// ---------------------------------------------------------------------------
// mma.sync NT GEMM:  C[M,N] = alpha * (A[M,K] @ B[N,K]^T)
// A = Ahi + Alo, B = Bhi + Blo (fp16 split); fp32 accumulate.
// NTERMS=3: AhBh + AlBh + AhBl (fp32-class).  NTERMS=2: AhBh + AlBh
// (= A·Bh; drops A·Blo, rel err ~2^-11 — used where downstream slack exists).
// Tile: 128x128, 8 warps (4 x 2), warp tile 32x64, K chunks of 64 fp16.
// grid = (N/128, M/128, batch). OUTH=1: write fp16 hi/lo; else fp32.
// ---------------------------------------------------------------------------
#define STG 65536                     // Ahi 16K | Alo 16K | Bhi 16K | Blo 16K
#define SMEM_TOTAL (2 * STG)          // 128 KB, double-buffered

template <int OUTH, int NTERMS>
__global__ void __launch_bounds__(256, 1) gemm_mma(
    const __half* __restrict__ Ahi, const __half* __restrict__ Alo,
    const __half* __restrict__ Bhi, const __half* __restrict__ Blo,
    float* __restrict__ C, __half* __restrict__ Chi, __half* __restrict__ Clo,
    int K, int lda, int ldb, int ldc,
    long long sA, long long sB, long long sC, float alpha)
{
    extern __shared__ __align__(1024) char smem[];
    const uint32_t sbase = smem_u32(smem);
    const int tid = threadIdx.x;
    const int wid = tid >> 5, lane = tid & 31;
    const long long bz = blockIdx.z;
    const int row0 = blockIdx.y * 128;
    const int col0 = blockIdx.x * 128;

    const char* gAhi = (const char*)(Ahi + bz * sA + (long long)row0 * lda);
    const char* gAlo = (const char*)(Alo + bz * sA + (long long)row0 * lda);
    const char* gBhi = (const char*)(Bhi + bz * sB + (long long)col0 * ldb);
    const char* gBlo = (const char*)(Blo + bz * sB + (long long)col0 * ldb);
    const long long ldab = (long long)lda * 2;
    const long long ldbb = (long long)ldb * 2;

    auto load_stage = [&](int c) {
        const uint32_t sb = sbase + ((c & 1) ? (uint32_t)STG : 0u);
        const long long kb = (long long)c * 128;    // 64 fp16 = 128 B per chunk
#pragma unroll
        for (int i = 0; i < 4; i++) {
            const int id = tid + (i << 8);          // 0..1023
            const uint32_t r = id >> 3, cb = (id & 7) << 4;
            const uint32_t off = swz((r << 7) + cb);
            const long long ga = (long long)r * ldab + kb + cb;
            const long long gb = (long long)r * ldbb + kb + cb;
            cpa16(sb + off,          gAhi + ga);
            cpa16(sb + 16384 + off,  gAlo + ga);
            cpa16(sb + 32768 + off,  gBhi + gb);
            if (NTERMS == 3) cpa16(sb + 49152 + off, gBlo + gb);
        }
        cpa_commit();
    };

    const int NC = K >> 6;
    const int warp_m = wid & 3;       // 4 warps down M (32 rows each)
    const int warp_n = wid >> 2;      // 2 warps across N (64 cols each)
    const int lrow = lane & 15;
    const uint32_t klane = (lane >> 4) << 4;

    float acc[2][8][4];
#pragma unroll
    for (int i = 0; i < 2; i++)
#pragma unroll
        for (int j = 0; j < 8; j++)
#pragma unroll
            for (int k = 0; k < 4; k++) acc[i][j][k] = 0.0f;

    load_stage(0);

    for (int c = 0; c < NC; c++) {
        if (c + 1 < NC) { load_stage(c + 1); cpa_wait<1>(); }
        else            { cpa_wait<0>(); }
        __syncthreads();

        const uint32_t sb = sbase + ((c & 1) ? (uint32_t)STG : 0u);
#pragma unroll
        for (int ks = 0; ks < 4; ks++) {
            const uint32_t kbyte = (ks << 5) + klane;
            uint32_t ah[2][4], al[2][4];
#pragma unroll
            for (int mt = 0; mt < 2; mt++) {
                const uint32_t off =
                    swz((uint32_t)((warp_m * 32 + mt * 16 + lrow) << 7) + kbyte);
                ldsm4(ah[mt], sb + off);
                ldsm4(al[mt], sb + 16384 + off);
            }
            uint32_t bh[4][4], bl[4][4];
#pragma unroll
            for (int ng = 0; ng < 4; ng++) {
                const uint32_t off =
                    swz((uint32_t)((warp_n * 64 + ng * 16 + lrow) << 7) + kbyte);
                ldsm4(bh[ng], sb + 32768 + off);
                if (NTERMS == 3) ldsm4(bl[ng], sb + 49152 + off);
            }
#pragma unroll
            for (int mt = 0; mt < 2; mt++)
#pragma unroll
                for (int nt = 0; nt < 8; nt++) {
                    const int ng = nt >> 1, j = nt & 1;
                    uint32_t B0[2] = { bh[ng][j], bh[ng][j + 2] };
                    mma16816(acc[mt][nt], ah[mt], B0);       // hi*hi
                    mma16816(acc[mt][nt], al[mt], B0);       // lo*hi
                    if (NTERMS == 3) {
                        uint32_t L0[2] = { bl[ng][j], bl[ng][j + 2] };
                        mma16816(acc[mt][nt], ah[mt], L0);   // hi*lo
                    }
                }
        }
        __syncthreads();
    }

    // Epilogue: c-frag rows lane/4 (+8), cols 2*(lane%4)+1
    const int rw = row0 + warp_m * 32 + (lane >> 2);
    const int cw = col0 + warp_n * 64 + (lane & 3) * 2;
#pragma unroll
    for (int mt = 0; mt < 2; mt++)
#pragma unroll
        for (int nt = 0; nt < 8; nt++) {
            const int cc = cw + nt * 8;
#pragma unroll
            for (int h = 0; h < 2; h++) {
                const int r = rw + mt * 16 + h * 8;
                const float v0 = alpha * acc[mt][nt][h * 2 + 0];
                const float v1 = alpha * acc[mt][nt][h * 2 + 1];
                const long long ci = bz * sC + (long long)r * ldc + cc;
                if (OUTH) {
                    const __half h0 = __float2half(v0);
                    const __half h1 = __float2half(v1);
                    ushort2 H, L;
                    H.x = __half_as_ushort(h0);
                    H.y = __half_as_ushort(h1);
                    L.x = __half_as_ushort(__float2half(v0 - __half2float(h0)));
                    L.y = __half_as_ushort(__float2half(v1 - __half2float(h1)));
                    *(ushort2*)&Chi[ci] = H;
                    *(ushort2*)&Clo[ci] = L;
                } else {
                    float2 o; o.x = v0; o.y = v1;
                    *(float2*)&C[ci] = o;
                }
            }
        }
}

// ---------------------------------------------------------------------------
// Fused fp32 -> fp16 hi/lo split of x + all 4 weights in ONE launch.
// Blocks [0,2048): x.  [2048,2304): Wq.  [2304,2560): Wk.
// [2560,2816): Wv.  [2816,3072): Wo.
// ---------------------------------------------------------------------------
__device__ __forceinline__ void split4(const float4 v, ushort4& H, ushort4& L) {
    const __half a = __float2half(v.x), b = __float2half(v.y);
    const __half c = __float2half(v.z), d = __float2half(v.w);
    H.x = __half_as_ushort(a); H.y = __half_as_ushort(b);
    H.z = __half_as_ushort(c); H.w = __half_as_ushort(d);
    L.x = __half_as_ushort(__float2half(v.x - __half2float(a)));
    L.y = __half_as_ushort(__float2half(v.y - __half2float(b)));
    L.z = __half_as_ushort(__float2half(v.z - __half2float(c)));
    L.w = __half_as_ushort(__float2half(v.w - __half2float(d)));
}

__global__ void __launch_bounds__(256) split_all(
    const float* __restrict__ x,  const float* __restrict__ Wq,
    const float* __restrict__ Wk, const float* __restrict__ Wv,
    const float* __restrict__ Wo,
    __half* __restrict__ xhi,  __half* __restrict__ xlo,
    __half* __restrict__ wqhi, __half* __restrict__ wqlo,
    __half* __restrict__ wkhi, __half* __restrict__ wklo,
    __half* __restrict__ wvhi, __half* __restrict__ wvlo,
    __half* __restrict__ wohi, __half* __restrict__ wolo)
{
    const int b = blockIdx.x;
    const int tid = threadIdx.x;
    const float4* in4;
    ushort4 *h4, *l4;
    long long n4, i0, stride;
    if (b < 2048) {
        in4 = (const float4*)x;  h4 = (ushort4*)xhi;  l4 = (ushort4*)xlo;
        n4 = (long long)MTOT * NXC / 4;  i0 = (long long)b * 256 + tid;  stride = 2048 * 256;
    } else {
        const int w = (b - 2048) >> 8;          // 0..3
        const int lb = (b - 2048) & 255;        // 0..255
        const float* W[4] = {Wq, Wk, Wv, Wo};
        __half* WH[4] = {wqhi, wkhi, wvhi, wohi};
        __half* WL[4] = {wqlo, wklo, wvlo, wolo};
        in4 = (const float4*)W[w];  h4 = (ushort4*)WH[w];  l4 = (ushort4*)WL[w];
        n4 = (long long)NHC * NXC / 4;  i0 = (long long)lb * 256 + tid;  stride = 256 * 256;
    }
    for (long long i = i0; i < n4; i += stride) {
        ushort4 H, L;
        split4(in4[i], H, L);
        h4[i] = H;
        l4[i] = L;
    }
}

// ---------------------------------------------------------------------------
// Row softmax over TT=2048 cols; output split to fp16 hi/lo.
// ---------------------------------------------------------------------------
__global__ void __launch_bounds__(256) softmax_split(
    const float* __restrict__ S, __half* __restrict__ Phi,
    __half* __restrict__ Plo)
{
    __shared__ float red[8];
    const float* p = S + (long long)blockIdx.x * TT;
    const int tid = threadIdx.x;

    float vals[8];
    float m = -3.4e38f;
#pragma unroll
    for (int i = 0; i < 8; ++i) {
        vals[i] = p[tid + 256 * i];
        m = fmaxf(m, vals[i]);
    }
#pragma unroll
    for (int o = 16; o > 0; o >>= 1) m = fmaxf(m, __shfl_xor_sync(0xffffffffu, m, o));
    if ((tid & 31) == 0) red[tid >> 5] = m;
    __syncthreads();
    float M = red[0];
#pragma unroll
    for (int i = 1; i < 8; ++i) M = fmaxf(M, red[i]);

    float s = 0.0f;
#pragma unroll
    for (int i = 0; i < 8; ++i) { vals[i] = __expf(vals[i] - M); s += vals[i]; }
#pragma unroll
    for (int o = 16; o > 0; o >>= 1) s += __shfl_xor_sync(0xffffffffu, s, o);
    __syncthreads();
    if ((tid & 31) == 0) red[tid >> 5] = s;
    __syncthreads();
    float tot = red[0];
#pragma unroll
    for (int i = 1; i < 8; ++i) tot += red[i];

    const float inv = 1.0f / tot;
    __half* ph = Phi + (long long)blockIdx.x * TT;
    __half* pl = Plo + (long long)blockIdx.x * TT;
#pragma unroll
    for (int i = 0; i < 8; ++i) {
        const float v = vals[i] * inv;
        const __half h = __float2half(v);
        ph[tid + 256 * i] = h;
        pl[tid + 256 * i] = __float2half(v - __half2float(h));
    }
}

// ---------------------------------------------------------------------------
// Launch sequence.  Order matters for ncu (captures the 4th launch):
//   1 split_all, 2 q(2T), 3 k(2T), 4 SCORES(2T), 5 v(3T), 6 softmax,
//   7 pv(2T), 8 out(3T)
// ---------------------------------------------------------------------------
extern "C" void kernel_launch(void* const* d_in, const int* in_sizes, int n_in,
                              void* d_out, int out_size)
{
    (void)in_sizes; (void)n_in; (void)out_size;
    const float* x  = (const float*)d_in[0];
    const float* Wq = (const float*)d_in[1];
    const float* Wk = (const float*)d_in[2];
    const float* Wv = (const float*)d_in[3];
    const float* Wo = (const float*)d_in[4];
    float* out = (float*)d_out;

    __half *xhi, *xlo, *wqhi, *wqlo, *wkhi, *wklo, *wvhi, *wvlo, *wohi, *wolo;
    __half *qhi, *qlo, *khi, *klo, *vthi, *vtlo, *phi, *plo, *ohi, *olo;
    float* S;
    cudaGetSymbolAddress((void**)&xhi, g_xhi);   cudaGetSymbolAddress((void**)&xlo, g_xlo);
    cudaGetSymbolAddress((void**)&wqhi, g_wqhi); cudaGetSymbolAddress((void**)&wqlo, g_wqlo);
    cudaGetSymbolAddress((void**)&wkhi, g_wkhi); cudaGetSymbolAddress((void**)&wklo, g_wklo);
    cudaGetSymbolAddress((void**)&wvhi, g_wvhi); cudaGetSymbolAddress((void**)&wvlo, g_wvlo);
    cudaGetSymbolAddress((void**)&wohi, g_wohi); cudaGetSymbolAddress((void**)&wolo, g_wolo);
    cudaGetSymbolAddress((void**)&qhi, g_qhi);   cudaGetSymbolAddress((void**)&qlo, g_qlo);
    cudaGetSymbolAddress((void**)&khi, g_khi);   cudaGetSymbolAddress((void**)&klo, g_klo);
    cudaGetSymbolAddress((void**)&vthi, g_vthi); cudaGetSymbolAddress((void**)&vtlo, g_vtlo);
    cudaGetSymbolAddress((void**)&phi, g_phi);   cudaGetSymbolAddress((void**)&plo, g_plo);
    cudaGetSymbolAddress((void**)&ohi, g_ohi);   cudaGetSymbolAddress((void**)&olo, g_olo);
    cudaGetSymbolAddress((void**)&S, g_s);

    cudaFuncSetAttribute(gemm_mma<0, 3>, cudaFuncAttributeMaxDynamicSharedMemorySize, SMEM_TOTAL);
    cudaFuncSetAttribute(gemm_mma<1, 3>, cudaFuncAttributeMaxDynamicSharedMemorySize, SMEM_TOTAL);
    cudaFuncSetAttribute(gemm_mma<0, 2>, cudaFuncAttributeMaxDynamicSharedMemorySize, SMEM_TOTAL);
    cudaFuncSetAttribute(gemm_mma<1, 2>, cudaFuncAttributeMaxDynamicSharedMemorySize, SMEM_TOTAL);

    const dim3 blk(256);

    // 1) fused splits (one launch)
    split_all<<<3072, blk>>>(x, Wq, Wk, Wv, Wo,
                             xhi, xlo, wqhi, wqlo, wkhi, wklo,
                             wvhi, wvlo, wohi, wolo);

    // 2-3) q = x @ Wqhi^T, k = x @ Wkhi^T   [16384 x 1024], 2-term
    {
        dim3 g(NHC / 128, MTOT / 128, 1);
        gemm_mma<1, 2><<<g, blk, SMEM_TOTAL>>>(xhi, xlo, wqhi, wqlo,
                                               nullptr, qhi, qlo,
                                               NXC, NXC, NXC, NHC, 0, 0, 0, 1.0f);
        gemm_mma<1, 2><<<g, blk, SMEM_TOTAL>>>(xhi, xlo, wkhi, wklo,
                                               nullptr, khi, klo,
                                               NXC, NXC, NXC, NHC, 0, 0, 0, 1.0f);
    }

    // 4) scores: S_b = (q_b @ khi_b^T)/sqrt(T), 2-term
    {
        dim3 g(TT / 128, TT / 128, BB);
        gemm_mma<0, 2><<<g, blk, SMEM_TOTAL>>>(qhi, qlo, khi, klo,
                                               S, nullptr, nullptr,
                                               NHC, NHC, NHC, TT,
                                               (long long)TT * NHC, (long long)TT * NHC,
                                               (long long)TT * TT, 0.022097086912079608f);
    }

    // 5) vT[h, b*T+t] = Wv @ x^T     [1024 x 16384], 3-term (output path)
    {
        dim3 g(MTOT / 128, NHC / 128, 1);
        gemm_mma<1, 3><<<g, blk, SMEM_TOTAL>>>(wvhi, wvlo, xhi, xlo,
                                               nullptr, vthi, vtlo,
                                               NXC, NXC, NXC, MTOT, 0, 0, 0, 1.0f);
    }

    // 6) softmax rows -> P (fp16 split)
    softmax_split<<<BB * TT, blk>>>(S, phi, plo);

    // 7) o_b = P_b @ vthi_b^T        [2048 x 1024] x 8, 2-term
    {
        dim3 g(NHC / 128, TT / 128, BB);
        gemm_mma<1, 2><<<g, blk, SMEM_TOTAL>>>(phi, plo, vthi, vtlo,
                                               nullptr, ohi, olo,
                                               TT, TT, MTOT, NHC,
                                               (long long)TT * TT, (long long)TT,
                                               (long long)TT * NHC, 1.0f);
    }

    // 8) out = o @ Wo^T              [16384 x 1024], 3-term (output path)
    {
        dim3 g(NHC / 128, MTOT / 128, 1);
        gemm_mma<0, 3><<<g, blk, SMEM_TOTAL>>>(ohi, olo, wohi, wolo,
                                               out, nullptr, nullptr,
                                               NHC, NHC, NHC, NHC, 0, 0, 0, 1.0f);
    }
}

// round 9
// speedup vs baseline: 1.5141x; 1.0861x over previous
#include <cuda_runtime.h>
#include <cuda_fp16.h>
#include <cstdint>

#define BB   8
#define TT   2048
#define NXC  1024
#define NHC  1024
#define MTOT (BB * TT)   // 16384

// ---------------------------------------------------------------------------
// Scratch (device globals — no allocation allowed anywhere)
// ---------------------------------------------------------------------------
__device__ __half g_xhi[(size_t)MTOT * NXC], g_xlo[(size_t)MTOT * NXC];
__device__ __half g_wqhi[NHC * NXC], g_wqlo[NHC * NXC];
__device__ __half g_wkhi[NHC * NXC], g_wklo[NHC * NXC];
__device__ __half g_wvhi[NHC * NXC], g_wvlo[NHC * NXC];
__device__ __half g_wohi[NHC * NHC], g_wolo[NHC * NHC];
__device__ __half g_qhi[(size_t)MTOT * NHC], g_qlo[(size_t)MTOT * NHC];
__device__ __half g_khi[(size_t)MTOT * NHC], g_klo[(size_t)MTOT * NHC];
__device__ __half g_vthi[(size_t)NHC * MTOT], g_vtlo[(size_t)NHC * MTOT];
__device__ float  g_s[(size_t)BB * TT * TT];
__device__ __half g_phi[(size_t)BB * TT * TT], g_plo[(size_t)BB * TT * TT];
__device__ __half g_ohi[(size_t)MTOT * NHC], g_olo[(size_t)MTOT * NHC];

// ---------------------------------------------------------------------------
// PTX helpers (sm_80-era only — must be valid under compute_103 virtual arch)
// ---------------------------------------------------------------------------
__device__ __forceinline__ uint32_t smem_u32(const void* p) {
    uint32_t a;
    asm("{ .reg .u64 t; cvta.to.shared.u64 t, %1; cvt.u32.u64 %0, t; }"
        : "=r"(a) : "l"(p));
    return a;
}
__device__ __forceinline__ void cpa16(uint32_t dst, const void* src) {
    asm volatile("cp.async.cg.shared.global [%0], [%1], 16;\n" :: "r"(dst), "l"(src));
}
__device__ __forceinline__ void cpa_commit() {
    asm volatile("cp.async.commit_group;\n" ::: "memory");
}
template <int N>
__device__ __forceinline__ void cpa_wait() {
    asm volatile("cp.async.wait_group %0;\n" :: "n"(N) : "memory");
}
__device__ __forceinline__ void ldsm4(uint32_t* r, uint32_t addr) {
    asm volatile("ldmatrix.sync.aligned.m8n8.x4.shared.b16 {%0,%1,%2,%3}, [%4];"
                 : "=r"(r[0]), "=r"(r[1]), "=r"(r[2]), "=r"(r[3]) : "r"(addr));
}
// fp16 inputs, fp32 accumulate
__device__ __forceinline__ void mma16816(float* d, const uint32_t* a, const uint32_t* b) {
    asm volatile(
        "mma.sync.aligned.m16n8k16.row.col.f32.f16.f16.f32 "
        "{%0,%1,%2,%3}, {%4,%5,%6,%7}, {%8,%9}, {%0,%1,%2,%3};"
        : "+f"(d[0]), "+f"(d[1]), "+f"(d[2]), "+f"(d[3])
        : "r"(a[0]), "r"(a[1]), "r"(a[2]), "r"(a[3]), "r"(b[0]), "r"(b[1]));
}
__device__ __forceinline__ uint32_t swz(uint32_t off) {
    return off ^ ((off >> 3) & 0x70);
}

// ---------------------------------------------------------------------------
// mma.sync NT GEMM:  C[M,N] = alpha * (A[M,K] @ B[N,K]^T)
// A = Ahi + Alo, B = Bhi + Blo (fp16 split); fp32 accumulate.
// NTERMS=3: AhBh + AlBh + AhBl (fp32-class).  NTERMS=2: AhBh + AlBh
// (= A·Bh; drops A·Blo, rel err ~2^-11 — calibrated ~1e-4 each on output).
// Tile: 128x128, 8 warps (4 x 2), warp tile 32x64, K chunks of 64 fp16.
// grid = (N/128, M/128, batch). OUTH=1: write fp16 hi/lo; else fp32.
// ---------------------------------------------------------------------------
#define STG 65536                     // Ahi 16K | Alo 16K | Bhi 16K | Blo 16K
#define SMEM_TOTAL (2 * STG)          // 128 KB, double-buffered

template <int OUTH, int NTERMS>
__global__ void __launch_bounds__(256, 1) gemm_mma(
    const __half* __restrict__ Ahi, const __half* __restrict__ Alo,
    const __half* __restrict__ Bhi, const __half* __restrict__ Blo,
    float* __restrict__ C, __half* __restrict__ Chi, __half* __restrict__ Clo,
    int K, int lda, int ldb, int ldc,
    long long sA, long long sB, long long sC, float alpha)
{
    extern __shared__ __align__(1024) char smem[];
    const uint32_t sbase = smem_u32(smem);
    const int tid = threadIdx.x;
    const int wid = tid >> 5, lane = tid & 31;
    const long long bz = blockIdx.z;
    const int row0 = blockIdx.y * 128;
    const int col0 = blockIdx.x * 128;

    const char* gAhi = (const char*)(Ahi + bz * sA + (long long)row0 * lda);
    const char* gAlo = (const char*)(Alo + bz * sA + (long long)row0 * lda);
    const char* gBhi = (const char*)(Bhi + bz * sB + (long long)col0 * ldb);
    const char* gBlo = (const char*)(Blo + bz * sB + (long long)col0 * ldb);
    const long long ldab = (long long)lda * 2;
    const long long ldbb = (long long)ldb * 2;

    auto load_stage = [&](int c) {
        const uint32_t sb = sbase + ((c & 1) ? (uint32_t)STG : 0u);
        const long long kb = (long long)c * 128;    // 64 fp16 = 128 B per chunk
#pragma unroll
        for (int i = 0; i < 4; i++) {
            const int id = tid + (i << 8);          // 0..1023
            const uint32_t r = id >> 3, cb = (id & 7) << 4;
            const uint32_t off = swz((r << 7) + cb);
            const long long ga = (long long)r * ldab + kb + cb;
            const long long gb = (long long)r * ldbb + kb + cb;
            cpa16(sb + off,          gAhi + ga);
            cpa16(sb + 16384 + off,  gAlo + ga);
            cpa16(sb + 32768 + off,  gBhi + gb);
            if (NTERMS == 3) cpa16(sb + 49152 + off, gBlo + gb);
        }
        cpa_commit();
    };

    const int NC = K >> 6;
    const int warp_m = wid & 3;       // 4 warps down M (32 rows each)
    const int warp_n = wid >> 2;      // 2 warps across N (64 cols each)
    const int lrow = lane & 15;
    const uint32_t klane = (lane >> 4) << 4;

    float acc[2][8][4];
#pragma unroll
    for (int i = 0; i < 2; i++)
#pragma unroll
        for (int j = 0; j < 8; j++)
#pragma unroll
            for (int k = 0; k < 4; k++) acc[i][j][k] = 0.0f;

    load_stage(0);

    for (int c = 0; c < NC; c++) {
        if (c + 1 < NC) { load_stage(c + 1); cpa_wait<1>(); }
        else            { cpa_wait<0>(); }
        __syncthreads();

        const uint32_t sb = sbase + ((c & 1) ? (uint32_t)STG : 0u);
#pragma unroll
        for (int ks = 0; ks < 4; ks++) {
            const uint32_t kbyte = (ks << 5) + klane;
            uint32_t ah[2][4], al[2][4];
#pragma unroll
            for (int mt = 0; mt < 2; mt++) {
                const uint32_t off =
                    swz((uint32_t)((warp_m * 32 + mt * 16 + lrow) << 7) + kbyte);
                ldsm4(ah[mt], sb + off);
                ldsm4(al[mt], sb + 16384 + off);
            }
            uint32_t bh[4][4], bl[4][4];
#pragma unroll
            for (int ng = 0; ng < 4; ng++) {
                const uint32_t off =
                    swz((uint32_t)((warp_n * 64 + ng * 16 + lrow) << 7) + kbyte);
                ldsm4(bh[ng], sb + 32768 + off);
                if (NTERMS == 3) ldsm4(bl[ng], sb + 49152 + off);
            }
#pragma unroll
            for (int mt = 0; mt < 2; mt++)
#pragma unroll
                for (int nt = 0; nt < 8; nt++) {
                    const int ng = nt >> 1, j = nt & 1;
                    uint32_t B0[2] = { bh[ng][j], bh[ng][j + 2] };
                    mma16816(acc[mt][nt], ah[mt], B0);       // hi*hi
                    mma16816(acc[mt][nt], al[mt], B0);       // lo*hi
                    if (NTERMS == 3) {
                        uint32_t L0[2] = { bl[ng][j], bl[ng][j + 2] };
                        mma16816(acc[mt][nt], ah[mt], L0);   // hi*lo
                    }
                }
        }
        __syncthreads();
    }

    // Epilogue: c-frag rows lane/4 (+8), cols 2*(lane%4)+1
    const int rw = row0 + warp_m * 32 + (lane >> 2);
    const int cw = col0 + warp_n * 64 + (lane & 3) * 2;
#pragma unroll
    for (int mt = 0; mt < 2; mt++)
#pragma unroll
        for (int nt = 0; nt < 8; nt++) {
            const int cc = cw + nt * 8;
#pragma unroll
            for (int h = 0; h < 2; h++) {
                const int r = rw + mt * 16 + h * 8;
                const float v0 = alpha * acc[mt][nt][h * 2 + 0];
                const float v1 = alpha * acc[mt][nt][h * 2 + 1];
                const long long ci = bz * sC + (long long)r * ldc + cc;
                if (OUTH) {
                    const __half h0 = __float2half(v0);
                    const __half h1 = __float2half(v1);
                    ushort2 H, L;
                    H.x = __half_as_ushort(h0);
                    H.y = __half_as_ushort(h1);
                    L.x = __half_as_ushort(__float2half(v0 - __half2float(h0)));
                    L.y = __half_as_ushort(__float2half(v1 - __half2float(h1)));
                    *(ushort2*)&Chi[ci] = H;
                    *(ushort2*)&Clo[ci] = L;
                } else {
                    float2 o; o.x = v0; o.y = v1;
                    *(float2*)&C[ci] = o;
                }
            }
        }
}

// ---------------------------------------------------------------------------
// Fused fp32 -> fp16 hi/lo split of x + all 4 weights in ONE launch.
// Blocks [0,2048): x.  [2048,2304): Wq.  [2304,2560): Wk.
// [2560,2816): Wv.  [2816,3072): Wo.
// ---------------------------------------------------------------------------
__device__ __forceinline__ void split4(const float4 v, ushort4& H, ushort4& L) {
    const __half a = __float2half(v.x), b = __float2half(v.y);
    const __half c = __float2half(v.z), d = __float2half(v.w);
    H.x = __half_as_ushort(a); H.y = __half_as_ushort(b);
    H.z = __half_as_ushort(c); H.w = __half_as_ushort(d);
    L.x = __half_as_ushort(__float2half(v.x - __half2float(a)));
    L.y = __half_as_ushort(__float2half(v.y - __half2float(b)));
    L.z = __half_as_ushort(__float2half(v.z - __half2float(c)));
    L.w = __half_as_ushort(__float2half(v.w - __half2float(d)));
}

__global__ void __launch_bounds__(256) split_all(
    const float* __restrict__ x,  const float* __restrict__ Wq,
    const float* __restrict__ Wk, const float* __restrict__ Wv,
    const float* __restrict__ Wo,
    __half* __restrict__ xhi,  __half* __restrict__ xlo,
    __half* __restrict__ wqhi, __half* __restrict__ wqlo,
    __half* __restrict__ wkhi, __half* __restrict__ wklo,
    __half* __restrict__ wvhi, __half* __restrict__ wvlo,
    __half* __restrict__ wohi, __half* __restrict__ wolo)
{
    const int b = blockIdx.x;
    const int tid = threadIdx.x;
    const float4* in4;
    ushort4 *h4, *l4;
    long long n4, i0, stride;
    if (b < 2048) {
        in4 = (const float4*)x;  h4 = (ushort4*)xhi;  l4 = (ushort4*)xlo;
        n4 = (long long)MTOT * NXC / 4;  i0 = (long long)b * 256 + tid;  stride = 2048 * 256;
    } else {
        const int w = (b - 2048) >> 8;          // 0..3
        const int lb = (b - 2048) & 255;        // 0..255
        const float* W[4] = {Wq, Wk, Wv, Wo};
        __half* WH[4] = {wqhi, wkhi, wvhi, wohi};
        __half* WL[4] = {wqlo, wklo, wvlo, wolo};
        in4 = (const float4*)W[w];  h4 = (ushort4*)WH[w];  l4 = (ushort4*)WL[w];
        n4 = (long long)NHC * NXC / 4;  i0 = (long long)lb * 256 + tid;  stride = 256 * 256;
    }
    for (long long i = i0; i < n4; i += stride) {
        ushort4 H, L;
        split4(in4[i], H, L);
        h4[i] = H;
        l4[i] = L;
    }
}

// ---------------------------------------------------------------------------
// Row softmax over TT=2048 cols; output split to fp16 hi/lo.
// ---------------------------------------------------------------------------
__global__ void __launch_bounds__(256) softmax_split(
    const float* __restrict__ S, __half* __restrict__ Phi,
    __half* __restrict__ Plo)
{
    __shared__ float red[8];
    const float* p = S + (long long)blockIdx.x * TT;
    const int tid = threadIdx.x;

    float vals[8];
    float m = -3.4e38f;
#pragma unroll
    for (int i = 0; i < 8; ++i) {
        vals[i] = p[tid + 256 * i];
        m = fmaxf(m, vals[i]);
    }
#pragma unroll
    for (int o = 16; o > 0; o >>= 1) m = fmaxf(m, __shfl_xor_sync(0xffffffffu, m, o));
    if ((tid & 31) == 0) red[tid >> 5] = m;
    __syncthreads();
    float M = red[0];
#pragma unroll
    for (int i = 1; i < 8; ++i) M = fmaxf(M, red[i]);

    float s = 0.0f;
#pragma unroll
    for (int i = 0; i < 8; ++i) { vals[i] = __expf(vals[i] - M); s += vals[i]; }
#pragma unroll
    for (int o = 16; o > 0; o >>= 1) s += __shfl_xor_sync(0xffffffffu, s, o);
    __syncthreads();
    if ((tid & 31) == 0) red[tid >> 5] = s;
    __syncthreads();
    float tot = red[0];
#pragma unroll
    for (int i = 1; i < 8; ++i) tot += red[i];

    const float inv = 1.0f / tot;
    __half* ph = Phi + (long long)blockIdx.x * TT;
    __half* pl = Plo + (long long)blockIdx.x * TT;
#pragma unroll
    for (int i = 0; i < 8; ++i) {
        const float v = vals[i] * inv;
        const __half h = __float2half(v);
        ph[tid + 256 * i] = h;
        pl[tid + 256 * i] = __float2half(v - __half2float(h));
    }
}

// ---------------------------------------------------------------------------
// Launch sequence.  Order matters for ncu (captures the 4th launch):
//   1 split_all, 2 q(2T), 3 k(2T), 4 SCORES(2T), 5 v(2T), 6 softmax,
//   7 pv(2T), 8 out(2T)
// ---------------------------------------------------------------------------
extern "C" void kernel_launch(void* const* d_in, const int* in_sizes, int n_in,
                              void* d_out, int out_size)
{
    (void)in_sizes; (void)n_in; (void)out_size;
    const float* x  = (const float*)d_in[0];
    const float* Wq = (const float*)d_in[1];
    const float* Wk = (const float*)d_in[2];
    const float* Wv = (const float*)d_in[3];
    const float* Wo = (const float*)d_in[4];
    float* out = (float*)d_out;

    __half *xhi, *xlo, *wqhi, *wqlo, *wkhi, *wklo, *wvhi, *wvlo, *wohi, *wolo;
    __half *qhi, *qlo, *khi, *klo, *vthi, *vtlo, *phi, *plo, *ohi, *olo;
    float* S;
    cudaGetSymbolAddress((void**)&xhi, g_xhi);   cudaGetSymbolAddress((void**)&xlo, g_xlo);
    cudaGetSymbolAddress((void**)&wqhi, g_wqhi); cudaGetSymbolAddress((void**)&wqlo, g_wqlo);
    cudaGetSymbolAddress((void**)&wkhi, g_wkhi); cudaGetSymbolAddress((void**)&wklo, g_wklo);
    cudaGetSymbolAddress((void**)&wvhi, g_wvhi); cudaGetSymbolAddress((void**)&wvlo, g_wvlo);
    cudaGetSymbolAddress((void**)&wohi, g_wohi); cudaGetSymbolAddress((void**)&wolo, g_wolo);
    cudaGetSymbolAddress((void**)&qhi, g_qhi);   cudaGetSymbolAddress((void**)&qlo, g_qlo);
    cudaGetSymbolAddress((void**)&khi, g_khi);   cudaGetSymbolAddress((void**)&klo, g_klo);
    cudaGetSymbolAddress((void**)&vthi, g_vthi); cudaGetSymbolAddress((void**)&vtlo, g_vtlo);
    cudaGetSymbolAddress((void**)&phi, g_phi);   cudaGetSymbolAddress((void**)&plo, g_plo);
    cudaGetSymbolAddress((void**)&ohi, g_ohi);   cudaGetSymbolAddress((void**)&olo, g_olo);
    cudaGetSymbolAddress((void**)&S, g_s);

    cudaFuncSetAttribute(gemm_mma<0, 2>, cudaFuncAttributeMaxDynamicSharedMemorySize, SMEM_TOTAL);
    cudaFuncSetAttribute(gemm_mma<1, 2>, cudaFuncAttributeMaxDynamicSharedMemorySize, SMEM_TOTAL);

    const dim3 blk(256);

    // 1) fused splits (one launch)
    split_all<<<3072, blk>>>(x, Wq, Wk, Wv, Wo,
                             xhi, xlo, wqhi, wqlo, wkhi, wklo,
                             wvhi, wvlo, wohi, wolo);

    // 2-3) q = x @ Wqhi^T, k = x @ Wkhi^T   [16384 x 1024], 2-term
    {
        dim3 g(NHC / 128, MTOT / 128, 1);
        gemm_mma<1, 2><<<g, blk, SMEM_TOTAL>>>(xhi, xlo, wqhi, wqlo,
                                               nullptr, qhi, qlo,
                                               NXC, NXC, NXC, NHC, 0, 0, 0, 1.0f);
        gemm_mma<1, 2><<<g, blk, SMEM_TOTAL>>>(xhi, xlo, wkhi, wklo,
                                               nullptr, khi, klo,
                                               NXC, NXC, NXC, NHC, 0, 0, 0, 1.0f);
    }

    // 4) scores: S_b = (q_b @ khi_b^T)/sqrt(T), 2-term
    {
        dim3 g(TT / 128, TT / 128, BB);
        gemm_mma<0, 2><<<g, blk, SMEM_TOTAL>>>(qhi, qlo, khi, klo,
                                               S, nullptr, nullptr,
                                               NHC, NHC, NHC, TT,
                                               (long long)TT * NHC, (long long)TT * NHC,
                                               (long long)TT * TT, 0.022097086912079608f);
    }

    // 5) vT[h, b*T+t] = Wv @ x^T     [1024 x 16384], 2-term
    {
        dim3 g(MTOT / 128, NHC / 128, 1);
        gemm_mma<1, 2><<<g, blk, SMEM_TOTAL>>>(wvhi, wvlo, xhi, xlo,
                                               nullptr, vthi, vtlo,
                                               NXC, NXC, NXC, MTOT, 0, 0, 0, 1.0f);
    }

    // 6) softmax rows -> P (fp16 split)
    softmax_split<<<BB * TT, blk>>>(S, phi, plo);

    // 7) o_b = P_b @ vthi_b^T        [2048 x 1024] x 8, 2-term
    {
        dim3 g(NHC / 128, TT / 128, BB);
        gemm_mma<1, 2><<<g, blk, SMEM_TOTAL>>>(phi, plo, vthi, vtlo,
                                               nullptr, ohi, olo,
                                               TT, TT, MTOT, NHC,
                                               (long long)TT * TT, (long long)TT,
                                               (long long)TT * NHC, 1.0f);
    }

    // 8) out = o @ Wohi^T            [16384 x 1024], 2-term
    {
        dim3 g(NHC / 128, MTOT / 128, 1);
        gemm_mma<0, 2><<<g, blk, SMEM_TOTAL>>>(ohi, olo, wohi, wolo,
                                               out, nullptr, nullptr,
                                               NHC, NHC, NHC, NHC, 0, 0, 0, 1.0f);
    }
}

// round 10
// speedup vs baseline: 1.9040x; 1.2575x over previous
#include <cuda_runtime.h>
#include <cuda_fp16.h>
#include <cstdint>

#define BB   8
#define TT   2048
#define NXC  1024
#define NHC  1024
#define MTOT (BB * TT)   // 16384

// ---------------------------------------------------------------------------
// Scratch (device globals — no allocation allowed anywhere)
// ---------------------------------------------------------------------------
__device__ __half g_xhi[(size_t)MTOT * NXC], g_xlo[(size_t)MTOT * NXC];
__device__ __half g_wqhi[NHC * NXC], g_wqlo[NHC * NXC];
__device__ __half g_wkhi[NHC * NXC], g_wklo[NHC * NXC];
__device__ __half g_wvhi[NHC * NXC], g_wvlo[NHC * NXC];
__device__ __half g_wohi[NHC * NHC], g_wolo[NHC * NHC];
__device__ __half g_qhi[(size_t)MTOT * NHC], g_qlo[(size_t)MTOT * NHC];
__device__ __half g_khi[(size_t)MTOT * NHC], g_klo[(size_t)MTOT * NHC];
__device__ __half g_vthi[(size_t)NHC * MTOT], g_vtlo[(size_t)NHC * MTOT];
__device__ float  g_s[(size_t)BB * TT * TT];
__device__ __half g_phi[(size_t)BB * TT * TT], g_plo[(size_t)BB * TT * TT];
__device__ __half g_ohi[(size_t)MTOT * NHC], g_olo[(size_t)MTOT * NHC];

// ---------------------------------------------------------------------------
// PTX helpers (sm_80-era only — must be valid under compute_103 virtual arch)
// ---------------------------------------------------------------------------
__device__ __forceinline__ uint32_t smem_u32(const void* p) {
    uint32_t a;
    asm("{ .reg .u64 t; cvta.to.shared.u64 t, %1; cvt.u32.u64 %0, t; }"
        : "=r"(a) : "l"(p));
    return a;
}
__device__ __forceinline__ void cpa16(uint32_t dst, const void* src) {
    asm volatile("cp.async.cg.shared.global [%0], [%1], 16;\n" :: "r"(dst), "l"(src));
}
__device__ __forceinline__ void cpa_commit() {
    asm volatile("cp.async.commit_group;\n" ::: "memory");
}
template <int N>
__device__ __forceinline__ void cpa_wait() {
    asm volatile("cp.async.wait_group %0;\n" :: "n"(N) : "memory");
}
__device__ __forceinline__ void ldsm4(uint32_t* r, uint32_t addr) {
    asm volatile("ldmatrix.sync.aligned.m8n8.x4.shared.b16 {%0,%1,%2,%3}, [%4];"
                 : "=r"(r[0]), "=r"(r[1]), "=r"(r[2]), "=r"(r[3]) : "r"(addr));
}
// fp16 inputs, fp32 accumulate
__device__ __forceinline__ void mma16816(float* d, const uint32_t* a, const uint32_t* b) {
    asm volatile(
        "mma.sync.aligned.m16n8k16.row.col.f32.f16.f16.f32 "
        "{%0,%1,%2,%3}, {%4,%5,%6,%7}, {%8,%9}, {%0,%1,%2,%3};"
        : "+f"(d[0]), "+f"(d[1]), "+f"(d[2]), "+f"(d[3])
        : "r"(a[0]), "r"(a[1]), "r"(a[2]), "r"(a[3]), "r"(b[0]), "r"(b[1]));
}
__device__ __forceinline__ uint32_t swz(uint32_t off) {
    return off ^ ((off >> 3) & 0x70);
}

// ---------------------------------------------------------------------------
// mma.sync NT GEMM:  C[M,N] = alpha * (A[M,K] @ B[N,K]^T)
// A = Ahi + Alo, B = Bhi + Blo (fp16 split); fp32 accumulate.
// NTERMS=3: AhBh + AlBh + AhBl (fp32-class).
// NTERMS=2: AhBh + AlBh  (drops A·Blo; ~0.9e-4 output contribution each).
// NTERMS=1: AhBh          (pure fp16 product; two dropped terms).
// Tile: 128x128, 8 warps (4 x 2), warp tile 32x64, K chunks of 64 fp16.
// grid = (N/128, M/128, batch). OUTH=1: write fp16 hi/lo; else fp32.
// ---------------------------------------------------------------------------
#define STG 65536                     // Ahi 16K | Alo 16K | Bhi 16K | Blo 16K
#define SMEM_TOTAL (2 * STG)          // 128 KB, double-buffered

template <int OUTH, int NTERMS>
__global__ void __launch_bounds__(256, 1) gemm_mma(
    const __half* __restrict__ Ahi, const __half* __restrict__ Alo,
    const __half* __restrict__ Bhi, const __half* __restrict__ Blo,
    float* __restrict__ C, __half* __restrict__ Chi, __half* __restrict__ Clo,
    int K, int lda, int ldb, int ldc,
    long long sA, long long sB, long long sC, float alpha)
{
    extern __shared__ __align__(1024) char smem[];
    const uint32_t sbase = smem_u32(smem);
    const int tid = threadIdx.x;
    const int wid = tid >> 5, lane = tid & 31;
    const long long bz = blockIdx.z;
    const int row0 = blockIdx.y * 128;
    const int col0 = blockIdx.x * 128;

    const char* gAhi = (const char*)(Ahi + bz * sA + (long long)row0 * lda);
    const char* gAlo = (const char*)(Alo + bz * sA + (long long)row0 * lda);
    const char* gBhi = (const char*)(Bhi + bz * sB + (long long)col0 * ldb);
    const char* gBlo = (const char*)(Blo + bz * sB + (long long)col0 * ldb);
    const long long ldab = (long long)lda * 2;
    const long long ldbb = (long long)ldb * 2;

    auto load_stage = [&](int c) {
        const uint32_t sb = sbase + ((c & 1) ? (uint32_t)STG : 0u);
        const long long kb = (long long)c * 128;    // 64 fp16 = 128 B per chunk
#pragma unroll
        for (int i = 0; i < 4; i++) {
            const int id = tid + (i << 8);          // 0..1023
            const uint32_t r = id >> 3, cb = (id & 7) << 4;
            const uint32_t off = swz((r << 7) + cb);
            const long long ga = (long long)r * ldab + kb + cb;
            const long long gb = (long long)r * ldbb + kb + cb;
            cpa16(sb + off,          gAhi + ga);
            if (NTERMS >= 2) cpa16(sb + 16384 + off, gAlo + ga);
            cpa16(sb + 32768 + off,  gBhi + gb);
            if (NTERMS == 3) cpa16(sb + 49152 + off, gBlo + gb);
        }
        cpa_commit();
    };

    const int NC = K >> 6;
    const int warp_m = wid & 3;       // 4 warps down M (32 rows each)
    const int warp_n = wid >> 2;      // 2 warps across N (64 cols each)
    const int lrow = lane & 15;
    const uint32_t klane = (lane >> 4) << 4;

    float acc[2][8][4];
#pragma unroll
    for (int i = 0; i < 2; i++)
#pragma unroll
        for (int j = 0; j < 8; j++)
#pragma unroll
            for (int k = 0; k < 4; k++) acc[i][j][k] = 0.0f;

    load_stage(0);

    for (int c = 0; c < NC; c++) {
        if (c + 1 < NC) { load_stage(c + 1); cpa_wait<1>(); }
        else            { cpa_wait<0>(); }
        __syncthreads();

        const uint32_t sb = sbase + ((c & 1) ? (uint32_t)STG : 0u);
#pragma unroll
        for (int ks = 0; ks < 4; ks++) {
            const uint32_t kbyte = (ks << 5) + klane;
            uint32_t ah[2][4], al[2][4];
#pragma unroll
            for (int mt = 0; mt < 2; mt++) {
                const uint32_t off =
                    swz((uint32_t)((warp_m * 32 + mt * 16 + lrow) << 7) + kbyte);
                ldsm4(ah[mt], sb + off);
                if (NTERMS >= 2) ldsm4(al[mt], sb + 16384 + off);
            }
            uint32_t bh[4][4], bl[4][4];
#pragma unroll
            for (int ng = 0; ng < 4; ng++) {
                const uint32_t off =
                    swz((uint32_t)((warp_n * 64 + ng * 16 + lrow) << 7) + kbyte);
                ldsm4(bh[ng], sb + 32768 + off);
                if (NTERMS == 3) ldsm4(bl[ng], sb + 49152 + off);
            }
#pragma unroll
            for (int mt = 0; mt < 2; mt++)
#pragma unroll
                for (int nt = 0; nt < 8; nt++) {
                    const int ng = nt >> 1, j = nt & 1;
                    uint32_t B0[2] = { bh[ng][j], bh[ng][j + 2] };
                    mma16816(acc[mt][nt], ah[mt], B0);       // hi*hi
                    if (NTERMS >= 2)
                        mma16816(acc[mt][nt], al[mt], B0);   // lo*hi
                    if (NTERMS == 3) {
                        uint32_t L0[2] = { bl[ng][j], bl[ng][j + 2] };
                        mma16816(acc[mt][nt], ah[mt], L0);   // hi*lo
                    }
                }
        }
        __syncthreads();
    }

    // Epilogue: c-frag rows lane/4 (+8), cols 2*(lane%4)+1
    const int rw = row0 + warp_m * 32 + (lane >> 2);
    const int cw = col0 + warp_n * 64 + (lane & 3) * 2;
#pragma unroll
    for (int mt = 0; mt < 2; mt++)
#pragma unroll
        for (int nt = 0; nt < 8; nt++) {
            const int cc = cw + nt * 8;
#pragma unroll
            for (int h = 0; h < 2; h++) {
                const int r = rw + mt * 16 + h * 8;
                const float v0 = alpha * acc[mt][nt][h * 2 + 0];
                const float v1 = alpha * acc[mt][nt][h * 2 + 1];
                const long long ci = bz * sC + (long long)r * ldc + cc;
                if (OUTH) {
                    const __half h0 = __float2half(v0);
                    const __half h1 = __float2half(v1);
                    ushort2 H, L;
                    H.x = __half_as_ushort(h0);
                    H.y = __half_as_ushort(h1);
                    L.x = __half_as_ushort(__float2half(v0 - __half2float(h0)));
                    L.y = __half_as_ushort(__float2half(v1 - __half2float(h1)));
                    *(ushort2*)&Chi[ci] = H;
                    *(ushort2*)&Clo[ci] = L;
                } else {
                    float2 o; o.x = v0; o.y = v1;
                    *(float2*)&C[ci] = o;
                }
            }
        }
}

// ---------------------------------------------------------------------------
// Fused fp32 -> fp16 hi/lo split of x + all 4 weights in ONE launch.
// Blocks [0,2048): x.  [2048,2304): Wq.  [2304,2560): Wk.
// [2560,2816): Wv.  [2816,3072): Wo.
// ---------------------------------------------------------------------------
__device__ __forceinline__ void split4(const float4 v, ushort4& H, ushort4& L) {
    const __half a = __float2half(v.x), b = __float2half(v.y);
    const __half c = __float2half(v.z), d = __float2half(v.w);
    H.x = __half_as_ushort(a); H.y = __half_as_ushort(b);
    H.z = __half_as_ushort(c); H.w = __half_as_ushort(d);
    L.x = __half_as_ushort(__float2half(v.x - __half2float(a)));
    L.y = __half_as_ushort(__float2half(v.y - __half2float(b)));
    L.z = __half_as_ushort(__float2half(v.z - __half2float(c)));
    L.w = __half_as_ushort(__float2half(v.w - __half2float(d)));
}

__global__ void __launch_bounds__(256) split_all(
    const float* __restrict__ x,  const float* __restrict__ Wq,
    const float* __restrict__ Wk, const float* __restrict__ Wv,
    const float* __restrict__ Wo,
    __half* __restrict__ xhi,  __half* __restrict__ xlo,
    __half* __restrict__ wqhi, __half* __restrict__ wqlo,
    __half* __restrict__ wkhi, __half* __restrict__ wklo,
    __half* __restrict__ wvhi, __half* __restrict__ wvlo,
    __half* __restrict__ wohi, __half* __restrict__ wolo)
{
    const int b = blockIdx.x;
    const int tid = threadIdx.x;
    const float4* in4;
    ushort4 *h4, *l4;
    long long n4, i0, stride;
    if (b < 2048) {
        in4 = (const float4*)x;  h4 = (ushort4*)xhi;  l4 = (ushort4*)xlo;
        n4 = (long long)MTOT * NXC / 4;  i0 = (long long)b * 256 + tid;  stride = 2048 * 256;
    } else {
        const int w = (b - 2048) >> 8;          // 0..3
        const int lb = (b - 2048) & 255;        // 0..255
        const float* W[4] = {Wq, Wk, Wv, Wo};
        __half* WH[4] = {wqhi, wkhi, wvhi, wohi};
        __half* WL[4] = {wqlo, wklo, wvlo, wolo};
        in4 = (const float4*)W[w];  h4 = (ushort4*)WH[w];  l4 = (ushort4*)WL[w];
        n4 = (long long)NHC * NXC / 4;  i0 = (long long)lb * 256 + tid;  stride = 256 * 256;
    }
    for (long long i = i0; i < n4; i += stride) {
        ushort4 H, L;
        split4(in4[i], H, L);
        h4[i] = H;
        l4[i] = L;
    }
}

// ---------------------------------------------------------------------------
// Row softmax over TT=2048 cols; output split to fp16 hi/lo.
// ---------------------------------------------------------------------------
__global__ void __launch_bounds__(256) softmax_split(
    const float* __restrict__ S, __half* __restrict__ Phi,
    __half* __restrict__ Plo)
{
    __shared__ float red[8];
    const float* p = S + (long long)blockIdx.x * TT;
    const int tid = threadIdx.x;

    float vals[8];
    float m = -3.4e38f;
#pragma unroll
    for (int i = 0; i < 8; ++i) {
        vals[i] = p[tid + 256 * i];
        m = fmaxf(m, vals[i]);
    }
#pragma unroll
    for (int o = 16; o > 0; o >>= 1) m = fmaxf(m, __shfl_xor_sync(0xffffffffu, m, o));
    if ((tid & 31) == 0) red[tid >> 5] = m;
    __syncthreads();
    float M = red[0];
#pragma unroll
    for (int i = 1; i < 8; ++i) M = fmaxf(M, red[i]);

    float s = 0.0f;
#pragma unroll
    for (int i = 0; i < 8; ++i) { vals[i] = __expf(vals[i] - M); s += vals[i]; }
#pragma unroll
    for (int o = 16; o > 0; o >>= 1) s += __shfl_xor_sync(0xffffffffu, s, o);
    __syncthreads();
    if ((tid & 31) == 0) red[tid >> 5] = s;
    __syncthreads();
    float tot = red[0];
#pragma unroll
    for (int i = 1; i < 8; ++i) tot += red[i];

    const float inv = 1.0f / tot;
    __half* ph = Phi + (long long)blockIdx.x * TT;
    __half* pl = Plo + (long long)blockIdx.x * TT;
#pragma unroll
    for (int i = 0; i < 8; ++i) {
        const float v = vals[i] * inv;
        const __half h = __float2half(v);
        ph[tid + 256 * i] = h;
        pl[tid + 256 * i] = __float2half(v - __half2float(h));
    }
}

// ---------------------------------------------------------------------------
// Launch sequence.  Order matters for ncu (captures the 4th launch):
//   1 split_all, 2 q(2T), 3 k(2T), 4 SCORES(1T), 5 v(2T), 6 softmax,
//   7 pv(1T), 8 out(2T)
// ---------------------------------------------------------------------------
extern "C" void kernel_launch(void* const* d_in, const int* in_sizes, int n_in,
                              void* d_out, int out_size)
{
    (void)in_sizes; (void)n_in; (void)out_size;
    const float* x  = (const float*)d_in[0];
    const float* Wq = (const float*)d_in[1];
    const float* Wk = (const float*)d_in[2];
    const float* Wv = (const float*)d_in[3];
    const float* Wo = (const float*)d_in[4];
    float* out = (float*)d_out;

    __half *xhi, *xlo, *wqhi, *wqlo, *wkhi, *wklo, *wvhi, *wvlo, *wohi, *wolo;
    __half *qhi, *qlo, *khi, *klo, *vthi, *vtlo, *phi, *plo, *ohi, *olo;
    float* S;
    cudaGetSymbolAddress((void**)&xhi, g_xhi);   cudaGetSymbolAddress((void**)&xlo, g_xlo);
    cudaGetSymbolAddress((void**)&wqhi, g_wqhi); cudaGetSymbolAddress((void**)&wqlo, g_wqlo);
    cudaGetSymbolAddress((void**)&wkhi, g_wkhi); cudaGetSymbolAddress((void**)&wklo, g_wklo);
    cudaGetSymbolAddress((void**)&wvhi, g_wvhi); cudaGetSymbolAddress((void**)&wvlo, g_wvlo);
    cudaGetSymbolAddress((void**)&wohi, g_wohi); cudaGetSymbolAddress((void**)&wolo, g_wolo);
    cudaGetSymbolAddress((void**)&qhi, g_qhi);   cudaGetSymbolAddress((void**)&qlo, g_qlo);
    cudaGetSymbolAddress((void**)&khi, g_khi);   cudaGetSymbolAddress((void**)&klo, g_klo);
    cudaGetSymbolAddress((void**)&vthi, g_vthi); cudaGetSymbolAddress((void**)&vtlo, g_vtlo);
    cudaGetSymbolAddress((void**)&phi, g_phi);   cudaGetSymbolAddress((void**)&plo, g_plo);
    cudaGetSymbolAddress((void**)&ohi, g_ohi);   cudaGetSymbolAddress((void**)&olo, g_olo);
    cudaGetSymbolAddress((void**)&S, g_s);

    cudaFuncSetAttribute(gemm_mma<0, 1>, cudaFuncAttributeMaxDynamicSharedMemorySize, SMEM_TOTAL);
    cudaFuncSetAttribute(gemm_mma<1, 1>, cudaFuncAttributeMaxDynamicSharedMemorySize, SMEM_TOTAL);
    cudaFuncSetAttribute(gemm_mma<0, 2>, cudaFuncAttributeMaxDynamicSharedMemorySize, SMEM_TOTAL);
    cudaFuncSetAttribute(gemm_mma<1, 2>, cudaFuncAttributeMaxDynamicSharedMemorySize, SMEM_TOTAL);

    const dim3 blk(256);

    // 1) fused splits (one launch)
    split_all<<<3072, blk>>>(x, Wq, Wk, Wv, Wo,
                             xhi, xlo, wqhi, wqlo, wkhi, wklo,
                             wvhi, wvlo, wohi, wolo);

    // 2-3) q = x @ Wqhi^T, k = x @ Wkhi^T   [16384 x 1024], 2-term
    {
        dim3 g(NHC / 128, MTOT / 128, 1);
        gemm_mma<1, 2><<<g, blk, SMEM_TOTAL>>>(xhi, xlo, wqhi, wqlo,
                                               nullptr, qhi, qlo,
                                               NXC, NXC, NXC, NHC, 0, 0, 0, 1.0f);
        gemm_mma<1, 2><<<g, blk, SMEM_TOTAL>>>(xhi, xlo, wkhi, wklo,
                                               nullptr, khi, klo,
                                               NXC, NXC, NXC, NHC, 0, 0, 0, 1.0f);
    }

    // 4) scores: S_b = (qhi_b @ khi_b^T)/sqrt(T), 1-term
    {
        dim3 g(TT / 128, TT / 128, BB);
        gemm_mma<0, 1><<<g, blk, SMEM_TOTAL>>>(qhi, qlo, khi, klo,
                                               S, nullptr, nullptr,
                                               NHC, NHC, NHC, TT,
                                               (long long)TT * NHC, (long long)TT * NHC,
                                               (long long)TT * TT, 0.022097086912079608f);
    }

    // 5) vT[h, b*T+t] = Wv @ x^T     [1024 x 16384], 2-term
    {
        dim3 g(MTOT / 128, NHC / 128, 1);
        gemm_mma<1, 2><<<g, blk, SMEM_TOTAL>>>(wvhi, wvlo, xhi, xlo,
                                               nullptr, vthi, vtlo,
                                               NXC, NXC, NXC, MTOT, 0, 0, 0, 1.0f);
    }

    // 6) softmax rows -> P (fp16 split)
    softmax_split<<<BB * TT, blk>>>(S, phi, plo);

    // 7) o_b = Phi_b @ vthi_b^T      [2048 x 1024] x 8, 1-term
    {
        dim3 g(NHC / 128, TT / 128, BB);
        gemm_mma<1, 1><<<g, blk, SMEM_TOTAL>>>(phi, plo, vthi, vtlo,
                                               nullptr, ohi, olo,
                                               TT, TT, MTOT, NHC,
                                               (long long)TT * TT, (long long)TT,
                                               (long long)TT * NHC, 1.0f);
    }

    // 8) out = o @ Wohi^T            [16384 x 1024], 2-term
    {
        dim3 g(NHC / 128, MTOT / 128, 1);
        gemm_mma<0, 2><<<g, blk, SMEM_TOTAL>>>(ohi, olo, wohi, wolo,
                                               out, nullptr, nullptr,
                                               NHC, NHC, NHC, NHC, 0, 0, 0, 1.0f);
    }
}

// round 11
// speedup vs baseline: 2.7208x; 1.4290x over previous
#include <cuda_runtime.h>
#include <cuda_fp16.h>
#include <cstdint>

#define BB   8
#define TT   2048
#define NXC  1024
#define NHC  1024
#define MTOT (BB * TT)   // 16384

// ---------------------------------------------------------------------------
// Scratch (device globals — no allocation allowed anywhere).
// Pure-fp16 pipeline: only hi halves exist.
// ---------------------------------------------------------------------------
__device__ __half g_xh[(size_t)MTOT * NXC];
__device__ __half g_wqh[NHC * NXC], g_wkh[NHC * NXC];
__device__ __half g_wvh[NHC * NXC], g_woh[NHC * NHC];
__device__ __half g_qh[(size_t)MTOT * NHC];
__device__ __half g_kh[(size_t)MTOT * NHC];
__device__ __half g_vth[(size_t)NHC * MTOT];
__device__ float  g_s[(size_t)BB * TT * TT];
__device__ __half g_ph[(size_t)BB * TT * TT];
__device__ __half g_oh[(size_t)MTOT * NHC];

// ---------------------------------------------------------------------------
// PTX helpers (sm_80-era only — must be valid under compute_103 virtual arch)
// ---------------------------------------------------------------------------
__device__ __forceinline__ uint32_t smem_u32(const void* p) {
    uint32_t a;
    asm("{ .reg .u64 t; cvta.to.shared.u64 t, %1; cvt.u32.u64 %0, t; }"
        : "=r"(a) : "l"(p));
    return a;
}
__device__ __forceinline__ void cpa16(uint32_t dst, const void* src) {
    asm volatile("cp.async.cg.shared.global [%0], [%1], 16;\n" :: "r"(dst), "l"(src));
}
__device__ __forceinline__ void cpa_commit() {
    asm volatile("cp.async.commit_group;\n" ::: "memory");
}
template <int N>
__device__ __forceinline__ void cpa_wait() {
    asm volatile("cp.async.wait_group %0;\n" :: "n"(N) : "memory");
}
__device__ __forceinline__ void ldsm4(uint32_t* r, uint32_t addr) {
    asm volatile("ldmatrix.sync.aligned.m8n8.x4.shared.b16 {%0,%1,%2,%3}, [%4];"
                 : "=r"(r[0]), "=r"(r[1]), "=r"(r[2]), "=r"(r[3]) : "r"(addr));
}
// fp16 inputs, fp32 accumulate
__device__ __forceinline__ void mma16816(float* d, const uint32_t* a, const uint32_t* b) {
    asm volatile(
        "mma.sync.aligned.m16n8k16.row.col.f32.f16.f16.f32 "
        "{%0,%1,%2,%3}, {%4,%5,%6,%7}, {%8,%9}, {%0,%1,%2,%3};"
        : "+f"(d[0]), "+f"(d[1]), "+f"(d[2]), "+f"(d[3])
        : "r"(a[0]), "r"(a[1]), "r"(a[2]), "r"(a[3]), "r"(b[0]), "r"(b[1]));
}
__device__ __forceinline__ uint32_t swz(uint32_t off) {
    return off ^ ((off >> 3) & 0x70);
}

// ---------------------------------------------------------------------------
// mma.sync NT GEMM (1-term fp16):  C[M,N] = alpha * (A[M,K] @ B[N,K]^T)
// fp32 accumulate. Tile: 128x128, 8 warps (4 x 2), warp tile 32x64,
// K chunks of 64 fp16, 2-stage cp.async double buffer (32 KB/stage).
// grid = (N/128, M/128, batch). OUTH=1: write fp16 C; else fp32 C.
// ---------------------------------------------------------------------------
#define A_OFF 0
#define B_OFF 16384
#define STG   32768                   // 32 KB per stage
#define SMEM_TOTAL (2 * STG)          // 64 KB

template <int OUTH>
__global__ void __launch_bounds__(256, 1) gemm_mma(
    const __half* __restrict__ A, const __half* __restrict__ B,
    float* __restrict__ C, __half* __restrict__ Ch,
    int K, int lda, int ldb, int ldc,
    long long sA, long long sB, long long sC, float alpha)
{
    extern __shared__ __align__(1024) char smem[];
    const uint32_t sbase = smem_u32(smem);
    const int tid = threadIdx.x;
    const int wid = tid >> 5, lane = tid & 31;
    const long long bz = blockIdx.z;
    const int row0 = blockIdx.y * 128;
    const int col0 = blockIdx.x * 128;

    const char* gA = (const char*)(A + bz * sA + (long long)row0 * lda);
    const char* gB = (const char*)(B + bz * sB + (long long)col0 * ldb);
    const long long ldab = (long long)lda * 2;
    const long long ldbb = (long long)ldb * 2;

    auto load_stage = [&](int c) {
        const uint32_t sb = sbase + ((c & 1) ? (uint32_t)STG : 0u);
        const long long kb = (long long)c * 128;    // 64 fp16 = 128 B per chunk
#pragma unroll
        for (int i = 0; i < 4; i++) {
            const int id = tid + (i << 8);          // 0..1023
            const uint32_t r = id >> 3, cb = (id & 7) << 4;
            const uint32_t off = swz((r << 7) + cb);
            cpa16(sb + A_OFF + off, gA + (long long)r * ldab + kb + cb);
            cpa16(sb + B_OFF + off, gB + (long long)r * ldbb + kb + cb);
        }
        cpa_commit();
    };

    const int NC = K >> 6;
    const int warp_m = wid & 3;       // 4 warps down M (32 rows each)
    const int warp_n = wid >> 2;      // 2 warps across N (64 cols each)
    const int lrow = lane & 15;
    const uint32_t klane = (lane >> 4) << 4;

    float acc[2][8][4];
#pragma unroll
    for (int i = 0; i < 2; i++)
#pragma unroll
        for (int j = 0; j < 8; j++)
#pragma unroll
            for (int k = 0; k < 4; k++) acc[i][j][k] = 0.0f;

    load_stage(0);

    for (int c = 0; c < NC; c++) {
        if (c + 1 < NC) { load_stage(c + 1); cpa_wait<1>(); }
        else            { cpa_wait<0>(); }
        __syncthreads();

        const uint32_t sb = sbase + ((c & 1) ? (uint32_t)STG : 0u);
#pragma unroll
        for (int ks = 0; ks < 4; ks++) {
            const uint32_t kbyte = (ks << 5) + klane;
            uint32_t ah[2][4];
#pragma unroll
            for (int mt = 0; mt < 2; mt++) {
                const uint32_t off =
                    swz((uint32_t)((warp_m * 32 + mt * 16 + lrow) << 7) + kbyte);
                ldsm4(ah[mt], sb + A_OFF + off);
            }
            uint32_t bh[4][4];
#pragma unroll
            for (int ng = 0; ng < 4; ng++) {
                const uint32_t off =
                    swz((uint32_t)((warp_n * 64 + ng * 16 + lrow) << 7) + kbyte);
                ldsm4(bh[ng], sb + B_OFF + off);
            }
#pragma unroll
            for (int mt = 0; mt < 2; mt++)
#pragma unroll
                for (int nt = 0; nt < 8; nt++) {
                    const int ng = nt >> 1, j = nt & 1;
                    uint32_t B0[2] = { bh[ng][j], bh[ng][j + 2] };
                    mma16816(acc[mt][nt], ah[mt], B0);
                }
        }
        __syncthreads();
    }

    // Epilogue: c-frag rows lane/4 (+8), cols 2*(lane%4)+1
    const int rw = row0 + warp_m * 32 + (lane >> 2);
    const int cw = col0 + warp_n * 64 + (lane & 3) * 2;
#pragma unroll
    for (int mt = 0; mt < 2; mt++)
#pragma unroll
        for (int nt = 0; nt < 8; nt++) {
            const int cc = cw + nt * 8;
#pragma unroll
            for (int h = 0; h < 2; h++) {
                const int r = rw + mt * 16 + h * 8;
                const float v0 = alpha * acc[mt][nt][h * 2 + 0];
                const float v1 = alpha * acc[mt][nt][h * 2 + 1];
                const long long ci = bz * sC + (long long)r * ldc + cc;
                if (OUTH) {
                    ushort2 H;
                    H.x = __half_as_ushort(__float2half(v0));
                    H.y = __half_as_ushort(__float2half(v1));
                    *(ushort2*)&Ch[ci] = H;
                } else {
                    float2 o; o.x = v0; o.y = v1;
                    *(float2*)&C[ci] = o;
                }
            }
        }
}

// ---------------------------------------------------------------------------
// Fused fp32 -> fp16 convert of x + all 4 weights in ONE launch.
// Blocks [0,2048): x.  [2048,2304): Wq.  [2304,2560): Wk.
// [2560,2816): Wv.  [2816,3072): Wo.
// ---------------------------------------------------------------------------
__global__ void __launch_bounds__(256) split_all(
    const float* __restrict__ x,  const float* __restrict__ Wq,
    const float* __restrict__ Wk, const float* __restrict__ Wv,
    const float* __restrict__ Wo,
    __half* __restrict__ xh,  __half* __restrict__ wqh,
    __half* __restrict__ wkh, __half* __restrict__ wvh,
    __half* __restrict__ woh)
{
    const int b = blockIdx.x;
    const int tid = threadIdx.x;
    const float4* in4;
    ushort4* h4;
    long long n4, i0, stride;
    if (b < 2048) {
        in4 = (const float4*)x;  h4 = (ushort4*)xh;
        n4 = (long long)MTOT * NXC / 4;  i0 = (long long)b * 256 + tid;  stride = 2048 * 256;
    } else {
        const int w = (b - 2048) >> 8;          // 0..3
        const int lb = (b - 2048) & 255;        // 0..255
        const float* W[4] = {Wq, Wk, Wv, Wo};
        __half* WH[4] = {wqh, wkh, wvh, woh};
        in4 = (const float4*)W[w];  h4 = (ushort4*)WH[w];
        n4 = (long long)NHC * NXC / 4;  i0 = (long long)lb * 256 + tid;  stride = 256 * 256;
    }
    for (long long i = i0; i < n4; i += stride) {
        const float4 v = in4[i];
        ushort4 H;
        H.x = __half_as_ushort(__float2half(v.x));
        H.y = __half_as_ushort(__float2half(v.y));
        H.z = __half_as_ushort(__float2half(v.z));
        H.w = __half_as_ushort(__float2half(v.w));
        h4[i] = H;
    }
}

// ---------------------------------------------------------------------------
// Row softmax over TT=2048 cols; fp16 output.
// ---------------------------------------------------------------------------
__global__ void __launch_bounds__(256) softmax_h(
    const float* __restrict__ S, __half* __restrict__ Ph)
{
    __shared__ float red[8];
    const float* p = S + (long long)blockIdx.x * TT;
    const int tid = threadIdx.x;

    float vals[8];
    float m = -3.4e38f;
#pragma unroll
    for (int i = 0; i < 8; ++i) {
        vals[i] = p[tid + 256 * i];
        m = fmaxf(m, vals[i]);
    }
#pragma unroll
    for (int o = 16; o > 0; o >>= 1) m = fmaxf(m, __shfl_xor_sync(0xffffffffu, m, o));
    if ((tid & 31) == 0) red[tid >> 5] = m;
    __syncthreads();
    float M = red[0];
#pragma unroll
    for (int i = 1; i < 8; ++i) M = fmaxf(M, red[i]);

    float s = 0.0f;
#pragma unroll
    for (int i = 0; i < 8; ++i) { vals[i] = __expf(vals[i] - M); s += vals[i]; }
#pragma unroll
    for (int o = 16; o > 0; o >>= 1) s += __shfl_xor_sync(0xffffffffu, s, o);
    __syncthreads();
    if ((tid & 31) == 0) red[tid >> 5] = s;
    __syncthreads();
    float tot = red[0];
#pragma unroll
    for (int i = 1; i < 8; ++i) tot += red[i];

    const float inv = 1.0f / tot;
    __half* ph = Ph + (long long)blockIdx.x * TT;
#pragma unroll
    for (int i = 0; i < 8; ++i)
        ph[tid + 256 * i] = __float2half(vals[i] * inv);
}

// ---------------------------------------------------------------------------
// Launch sequence.  Order matters for ncu (captures the 4th launch):
//   1 split_all, 2 q, 3 k, 4 SCORES, 5 v, 6 softmax, 7 pv, 8 out
// ---------------------------------------------------------------------------
extern "C" void kernel_launch(void* const* d_in, const int* in_sizes, int n_in,
                              void* d_out, int out_size)
{
    (void)in_sizes; (void)n_in; (void)out_size;
    const float* x  = (const float*)d_in[0];
    const float* Wq = (const float*)d_in[1];
    const float* Wk = (const float*)d_in[2];
    const float* Wv = (const float*)d_in[3];
    const float* Wo = (const float*)d_in[4];
    float* out = (float*)d_out;

    __half *xh, *wqh, *wkh, *wvh, *woh, *qh, *kh, *vth, *ph, *oh;
    float* S;
    cudaGetSymbolAddress((void**)&xh, g_xh);
    cudaGetSymbolAddress((void**)&wqh, g_wqh);
    cudaGetSymbolAddress((void**)&wkh, g_wkh);
    cudaGetSymbolAddress((void**)&wvh, g_wvh);
    cudaGetSymbolAddress((void**)&woh, g_woh);
    cudaGetSymbolAddress((void**)&qh, g_qh);
    cudaGetSymbolAddress((void**)&kh, g_kh);
    cudaGetSymbolAddress((void**)&vth, g_vth);
    cudaGetSymbolAddress((void**)&ph, g_ph);
    cudaGetSymbolAddress((void**)&oh, g_oh);
    cudaGetSymbolAddress((void**)&S, g_s);

    cudaFuncSetAttribute(gemm_mma<0>, cudaFuncAttributeMaxDynamicSharedMemorySize, SMEM_TOTAL);
    cudaFuncSetAttribute(gemm_mma<1>, cudaFuncAttributeMaxDynamicSharedMemorySize, SMEM_TOTAL);

    const dim3 blk(256);

    // 1) fused converts (one launch)
    split_all<<<3072, blk>>>(x, Wq, Wk, Wv, Wo, xh, wqh, wkh, wvh, woh);

    // 2-3) q = x @ Wq^T, k = x @ Wk^T   [16384 x 1024]
    {
        dim3 g(NHC / 128, MTOT / 128, 1);
        gemm_mma<1><<<g, blk, SMEM_TOTAL>>>(xh, wqh, nullptr, qh,
                                            NXC, NXC, NXC, NHC, 0, 0, 0, 1.0f);
        gemm_mma<1><<<g, blk, SMEM_TOTAL>>>(xh, wkh, nullptr, kh,
                                            NXC, NXC, NXC, NHC, 0, 0, 0, 1.0f);
    }

    // 4) scores: S_b = (q_b @ k_b^T)/sqrt(T)
    {
        dim3 g(TT / 128, TT / 128, BB);
        gemm_mma<0><<<g, blk, SMEM_TOTAL>>>(qh, kh, S, nullptr,
                                            NHC, NHC, NHC, TT,
                                            (long long)TT * NHC, (long long)TT * NHC,
                                            (long long)TT * TT, 0.022097086912079608f);
    }

    // 5) vT[h, b*T+t] = Wv @ x^T     [1024 x 16384]
    {
        dim3 g(MTOT / 128, NHC / 128, 1);
        gemm_mma<1><<<g, blk, SMEM_TOTAL>>>(wvh, xh, nullptr, vth,
                                            NXC, NXC, NXC, MTOT, 0, 0, 0, 1.0f);
    }

    // 6) softmax rows -> P (fp16)
    softmax_h<<<BB * TT, blk>>>(S, ph);

    // 7) o_b = P_b @ vT_b^T          [2048 x 1024] x 8
    {
        dim3 g(NHC / 128, TT / 128, BB);
        gemm_mma<1><<<g, blk, SMEM_TOTAL>>>(ph, vth, nullptr, oh,
                                            TT, TT, MTOT, NHC,
                                            (long long)TT * TT, (long long)TT,
                                            (long long)TT * NHC, 1.0f);
    }

    // 8) out = o @ Wo^T              [16384 x 1024]
    {
        dim3 g(NHC / 128, MTOT / 128, 1);
        gemm_mma<0><<<g, blk, SMEM_TOTAL>>>(oh, woh, out, nullptr,
                                            NHC, NHC, NHC, NHC, 0, 0, 0, 1.0f);
    }
}

// round 12
// speedup vs baseline: 3.1818x; 1.1694x over previous
#include <cuda_runtime.h>
#include <cuda_fp16.h>
#include <cstdint>

#define BB   8
#define TT   2048
#define NXC  1024
#define NHC  1024
#define MTOT (BB * TT)   // 16384

// ---------------------------------------------------------------------------
// Scratch (device globals — no allocation allowed anywhere).
// Pure-fp16 pipeline: only hi halves exist.
// ---------------------------------------------------------------------------
__device__ __half g_xh[(size_t)MTOT * NXC];
__device__ __half g_wqh[NHC * NXC], g_wkh[NHC * NXC];
__device__ __half g_wvh[NHC * NXC], g_woh[NHC * NHC];
__device__ __half g_qh[(size_t)MTOT * NHC];
__device__ __half g_kh[(size_t)MTOT * NHC];
__device__ __half g_vth[(size_t)NHC * MTOT];
__device__ float  g_s[(size_t)BB * TT * TT];
__device__ __half g_ph[(size_t)BB * TT * TT];
__device__ __half g_oh[(size_t)MTOT * NHC];

// ---------------------------------------------------------------------------
// PTX helpers (sm_80-era only — must be valid under compute_103 virtual arch)
// ---------------------------------------------------------------------------
__device__ __forceinline__ uint32_t smem_u32(const void* p) {
    uint32_t a;
    asm("{ .reg .u64 t; cvta.to.shared.u64 t, %1; cvt.u32.u64 %0, t; }"
        : "=r"(a) : "l"(p));
    return a;
}
__device__ __forceinline__ void cpa16(uint32_t dst, const void* src) {
    asm volatile("cp.async.cg.shared.global [%0], [%1], 16;\n" :: "r"(dst), "l"(src));
}
__device__ __forceinline__ void cpa_commit() {
    asm volatile("cp.async.commit_group;\n" ::: "memory");
}
template <int N>
__device__ __forceinline__ void cpa_wait() {
    asm volatile("cp.async.wait_group %0;\n" :: "n"(N) : "memory");
}
__device__ __forceinline__ void ldsm4(uint32_t* r, uint32_t addr) {
    asm volatile("ldmatrix.sync.aligned.m8n8.x4.shared.b16 {%0,%1,%2,%3}, [%4];"
                 : "=r"(r[0]), "=r"(r[1]), "=r"(r[2]), "=r"(r[3]) : "r"(addr));
}
// fp16 inputs, fp32 accumulate
__device__ __forceinline__ void mma16816(float* d, const uint32_t* a, const uint32_t* b) {
    asm volatile(
        "mma.sync.aligned.m16n8k16.row.col.f32.f16.f16.f32 "
        "{%0,%1,%2,%3}, {%4,%5,%6,%7}, {%8,%9}, {%0,%1,%2,%3};"
        : "+f"(d[0]), "+f"(d[1]), "+f"(d[2]), "+f"(d[3])
        : "r"(a[0]), "r"(a[1]), "r"(a[2]), "r"(a[3]), "r"(b[0]), "r"(b[1]));
}
__device__ __forceinline__ uint32_t swz(uint32_t off) {
    return off ^ ((off >> 3) & 0x70);
}

// ---------------------------------------------------------------------------
// mma.sync NT GEMM (1-term fp16):  C[M,N] = alpha * (A[M,K] @ B[N,K]^T)
// fp32 accumulate. Tile: 128x128, 8 warps (4 x 2), warp tile 32x64,
// K chunks of 64 fp16, 2-stage cp.async double buffer (32 KB/stage).
// __launch_bounds__(256, 2): 64 KB smem/CTA -> 2 CTAs/SM (4 warps/SMSP)
// for cross-CTA latency hiding; true reg need ~110, fits 128 w/o spills.
// grid = (N/128, M/128, batch). OUTH=1: write fp16 C; else fp32 C.
// ---------------------------------------------------------------------------
#define A_OFF 0
#define B_OFF 16384
#define STG   32768                   // 32 KB per stage
#define SMEM_TOTAL (2 * STG)          // 64 KB

template <int OUTH>
__global__ void __launch_bounds__(256, 2) gemm_mma(
    const __half* __restrict__ A, const __half* __restrict__ B,
    float* __restrict__ C, __half* __restrict__ Ch,
    int K, int lda, int ldb, int ldc,
    long long sA, long long sB, long long sC, float alpha)
{
    extern __shared__ __align__(1024) char smem[];
    const uint32_t sbase = smem_u32(smem);
    const int tid = threadIdx.x;
    const int wid = tid >> 5, lane = tid & 31;
    const long long bz = blockIdx.z;
    const int row0 = blockIdx.y * 128;
    const int col0 = blockIdx.x * 128;

    const char* gA = (const char*)(A + bz * sA + (long long)row0 * lda);
    const char* gB = (const char*)(B + bz * sB + (long long)col0 * ldb);
    const long long ldab = (long long)lda * 2;
    const long long ldbb = (long long)ldb * 2;

    auto load_stage = [&](int c) {
        const uint32_t sb = sbase + ((c & 1) ? (uint32_t)STG : 0u);
        const long long kb = (long long)c * 128;    // 64 fp16 = 128 B per chunk
#pragma unroll
        for (int i = 0; i < 4; i++) {
            const int id = tid + (i << 8);          // 0..1023
            const uint32_t r = id >> 3, cb = (id & 7) << 4;
            const uint32_t off = swz((r << 7) + cb);
            cpa16(sb + A_OFF + off, gA + (long long)r * ldab + kb + cb);
            cpa16(sb + B_OFF + off, gB + (long long)r * ldbb + kb + cb);
        }
        cpa_commit();
    };

    const int NC = K >> 6;
    const int warp_m = wid & 3;       // 4 warps down M (32 rows each)
    const int warp_n = wid >> 2;      // 2 warps across N (64 cols each)
    const int lrow = lane & 15;
    const uint32_t klane = (lane >> 4) << 4;

    float acc[2][8][4];
#pragma unroll
    for (int i = 0; i < 2; i++)
#pragma unroll
        for (int j = 0; j < 8; j++)
#pragma unroll
            for (int k = 0; k < 4; k++) acc[i][j][k] = 0.0f;

    load_stage(0);

    for (int c = 0; c < NC; c++) {
        if (c + 1 < NC) { load_stage(c + 1); cpa_wait<1>(); }
        else            { cpa_wait<0>(); }
        __syncthreads();

        const uint32_t sb = sbase + ((c & 1) ? (uint32_t)STG : 0u);
#pragma unroll
        for (int ks = 0; ks < 4; ks++) {
            const uint32_t kbyte = (ks << 5) + klane;
            uint32_t ah[2][4];
#pragma unroll
            for (int mt = 0; mt < 2; mt++) {
                const uint32_t off =
                    swz((uint32_t)((warp_m * 32 + mt * 16 + lrow) << 7) + kbyte);
                ldsm4(ah[mt], sb + A_OFF + off);
            }
            uint32_t bh[4][4];
#pragma unroll
            for (int ng = 0; ng < 4; ng++) {
                const uint32_t off =
                    swz((uint32_t)((warp_n * 64 + ng * 16 + lrow) << 7) + kbyte);
                ldsm4(bh[ng], sb + B_OFF + off);
            }
#pragma unroll
            for (int mt = 0; mt < 2; mt++)
#pragma unroll
                for (int nt = 0; nt < 8; nt++) {
                    const int ng = nt >> 1, j = nt & 1;
                    uint32_t B0[2] = { bh[ng][j], bh[ng][j + 2] };
                    mma16816(acc[mt][nt], ah[mt], B0);
                }
        }
        __syncthreads();
    }

    // Epilogue: c-frag rows lane/4 (+8), cols 2*(lane%4)+1
    const int rw = row0 + warp_m * 32 + (lane >> 2);
    const int cw = col0 + warp_n * 64 + (lane & 3) * 2;
#pragma unroll
    for (int mt = 0; mt < 2; mt++)
#pragma unroll
        for (int nt = 0; nt < 8; nt++) {
            const int cc = cw + nt * 8;
#pragma unroll
            for (int h = 0; h < 2; h++) {
                const int r = rw + mt * 16 + h * 8;
                const float v0 = alpha * acc[mt][nt][h * 2 + 0];
                const float v1 = alpha * acc[mt][nt][h * 2 + 1];
                const long long ci = bz * sC + (long long)r * ldc + cc;
                if (OUTH) {
                    ushort2 H;
                    H.x = __half_as_ushort(__float2half(v0));
                    H.y = __half_as_ushort(__float2half(v1));
                    *(ushort2*)&Ch[ci] = H;
                } else {
                    float2 o; o.x = v0; o.y = v1;
                    *(float2*)&C[ci] = o;
                }
            }
        }
}

// ---------------------------------------------------------------------------
// Fused fp32 -> fp16 convert of x + all 4 weights in ONE launch.
// Blocks [0,2048): x.  [2048,2304): Wq.  [2304,2560): Wk.
// [2560,2816): Wv.  [2816,3072): Wo.
// ---------------------------------------------------------------------------
__global__ void __launch_bounds__(256) split_all(
    const float* __restrict__ x,  const float* __restrict__ Wq,
    const float* __restrict__ Wk, const float* __restrict__ Wv,
    const float* __restrict__ Wo,
    __half* __restrict__ xh,  __half* __restrict__ wqh,
    __half* __restrict__ wkh, __half* __restrict__ wvh,
    __half* __restrict__ woh)
{
    const int b = blockIdx.x;
    const int tid = threadIdx.x;
    const float4* in4;
    ushort4* h4;
    long long n4, i0, stride;
    if (b < 2048) {
        in4 = (const float4*)x;  h4 = (ushort4*)xh;
        n4 = (long long)MTOT * NXC / 4;  i0 = (long long)b * 256 + tid;  stride = 2048 * 256;
    } else {
        const int w = (b - 2048) >> 8;          // 0..3
        const int lb = (b - 2048) & 255;        // 0..255
        const float* W[4] = {Wq, Wk, Wv, Wo};
        __half* WH[4] = {wqh, wkh, wvh, woh};
        in4 = (const float4*)W[w];  h4 = (ushort4*)WH[w];
        n4 = (long long)NHC * NXC / 4;  i0 = (long long)lb * 256 + tid;  stride = 256 * 256;
    }
    for (long long i = i0; i < n4; i += stride) {
        const float4 v = in4[i];
        ushort4 H;
        H.x = __half_as_ushort(__float2half(v.x));
        H.y = __half_as_ushort(__float2half(v.y));
        H.z = __half_as_ushort(__float2half(v.z));
        H.w = __half_as_ushort(__float2half(v.w));
        h4[i] = H;
    }
}

// ---------------------------------------------------------------------------
// Row softmax over TT=2048 cols; fp16 output.
// ---------------------------------------------------------------------------
__global__ void __launch_bounds__(256) softmax_h(
    const float* __restrict__ S, __half* __restrict__ Ph)
{
    __shared__ float red[8];
    const float* p = S + (long long)blockIdx.x * TT;
    const int tid = threadIdx.x;

    float vals[8];
    float m = -3.4e38f;
#pragma unroll
    for (int i = 0; i < 8; ++i) {
        vals[i] = p[tid + 256 * i];
        m = fmaxf(m, vals[i]);
    }
#pragma unroll
    for (int o = 16; o > 0; o >>= 1) m = fmaxf(m, __shfl_xor_sync(0xffffffffu, m, o));
    if ((tid & 31) == 0) red[tid >> 5] = m;
    __syncthreads();
    float M = red[0];
#pragma unroll
    for (int i = 1; i < 8; ++i) M = fmaxf(M, red[i]);

    float s = 0.0f;
#pragma unroll
    for (int i = 0; i < 8; ++i) { vals[i] = __expf(vals[i] - M); s += vals[i]; }
#pragma unroll
    for (int o = 16; o > 0; o >>= 1) s += __shfl_xor_sync(0xffffffffu, s, o);
    __syncthreads();
    if ((tid & 31) == 0) red[tid >> 5] = s;
    __syncthreads();
    float tot = red[0];
#pragma unroll
    for (int i = 1; i < 8; ++i) tot += red[i];

    const float inv = 1.0f / tot;
    __half* ph = Ph + (long long)blockIdx.x * TT;
#pragma unroll
    for (int i = 0; i < 8; ++i)
        ph[tid + 256 * i] = __float2half(vals[i] * inv);
}

// ---------------------------------------------------------------------------
// Launch sequence.  Order matters for ncu (captures the 4th launch):
//   1 split_all, 2 q, 3 k, 4 SCORES, 5 v, 6 softmax, 7 pv, 8 out
// ---------------------------------------------------------------------------
extern "C" void kernel_launch(void* const* d_in, const int* in_sizes, int n_in,
                              void* d_out, int out_size)
{
    (void)in_sizes; (void)n_in; (void)out_size;
    const float* x  = (const float*)d_in[0];
    const float* Wq = (const float*)d_in[1];
    const float* Wk = (const float*)d_in[2];
    const float* Wv = (const float*)d_in[3];
    const float* Wo = (const float*)d_in[4];
    float* out = (float*)d_out;

    __half *xh, *wqh, *wkh, *wvh, *woh, *qh, *kh, *vth, *ph, *oh;
    float* S;
    cudaGetSymbolAddress((void**)&xh, g_xh);
    cudaGetSymbolAddress((void**)&wqh, g_wqh);
    cudaGetSymbolAddress((void**)&wkh, g_wkh);
    cudaGetSymbolAddress((void**)&wvh, g_wvh);
    cudaGetSymbolAddress((void**)&woh, g_woh);
    cudaGetSymbolAddress((void**)&qh, g_qh);
    cudaGetSymbolAddress((void**)&kh, g_kh);
    cudaGetSymbolAddress((void**)&vth, g_vth);
    cudaGetSymbolAddress((void**)&ph, g_ph);
    cudaGetSymbolAddress((void**)&oh, g_oh);
    cudaGetSymbolAddress((void**)&S, g_s);

    cudaFuncSetAttribute(gemm_mma<0>, cudaFuncAttributeMaxDynamicSharedMemorySize, SMEM_TOTAL);
    cudaFuncSetAttribute(gemm_mma<1>, cudaFuncAttributeMaxDynamicSharedMemorySize, SMEM_TOTAL);

    const dim3 blk(256);

    // 1) fused converts (one launch)
    split_all<<<3072, blk>>>(x, Wq, Wk, Wv, Wo, xh, wqh, wkh, wvh, woh);

    // 2-3) q = x @ Wq^T, k = x @ Wk^T   [16384 x 1024]
    {
        dim3 g(NHC / 128, MTOT / 128, 1);
        gemm_mma<1><<<g, blk, SMEM_TOTAL>>>(xh, wqh, nullptr, qh,
                                            NXC, NXC, NXC, NHC, 0, 0, 0, 1.0f);
        gemm_mma<1><<<g, blk, SMEM_TOTAL>>>(xh, wkh, nullptr, kh,
                                            NXC, NXC, NXC, NHC, 0, 0, 0, 1.0f);
    }

    // 4) scores: S_b = (q_b @ k_b^T)/sqrt(T)
    {
        dim3 g(TT / 128, TT / 128, BB);
        gemm_mma<0><<<g, blk, SMEM_TOTAL>>>(qh, kh, S, nullptr,
                                            NHC, NHC, NHC, TT,
                                            (long long)TT * NHC, (long long)TT * NHC,
                                            (long long)TT * TT, 0.022097086912079608f);
    }

    // 5) vT[h, b*T+t] = Wv @ x^T     [1024 x 16384]
    {
        dim3 g(MTOT / 128, NHC / 128, 1);
        gemm_mma<1><<<g, blk, SMEM_TOTAL>>>(wvh, xh, nullptr, vth,
                                            NXC, NXC, NXC, MTOT, 0, 0, 0, 1.0f);
    }

    // 6) softmax rows -> P (fp16)
    softmax_h<<<BB * TT, blk>>>(S, ph);

    // 7) o_b = P_b @ vT_b^T          [2048 x 1024] x 8
    {
        dim3 g(NHC / 128, TT / 128, BB);
        gemm_mma<1><<<g, blk, SMEM_TOTAL>>>(ph, vth, nullptr, oh,
                                            TT, TT, MTOT, NHC,
                                            (long long)TT * TT, (long long)TT,
                                            (long long)TT * NHC, 1.0f);
    }

    // 8) out = o @ Wo^T              [16384 x 1024]
    {
        dim3 g(NHC / 128, MTOT / 128, 1);
        gemm_mma<0><<<g, blk, SMEM_TOTAL>>>(oh, woh, out, nullptr,
                                            NHC, NHC, NHC, NHC, 0, 0, 0, 1.0f);
    }
}